// round 2
// baseline (speedup 1.0000x reference)
#include <cuda_runtime.h>
#include <math.h>

// Problem constants
#define kB   512
#define kN   256
#define kC   128
#define kH   4
#define kHD  32
#define kNW  64

// Scratch (device globals: no runtime allocation allowed)
__device__ __align__(16) float g_q[(size_t)kB * kH * kN * kHD];
__device__ __align__(16) float g_k[(size_t)kB * kH * kN * kHD];
__device__ __align__(16) float g_v[(size_t)kB * kH * kN * kHD];
__device__ __align__(16) float g_bias[(size_t)kH * kN * kN];
__device__ __align__(16) float g_ao[(size_t)kB * kN * kC];

// ---------------------------------------------------------------------------
// Bias gather: g_bias[h][n][m] = table[rel_idx[n*256+m]][h]
// ---------------------------------------------------------------------------
__global__ __launch_bounds__(256) void bias_gather_kernel(
    const float* __restrict__ table, const int* __restrict__ ridx)
{
    int idx = blockIdx.x * 256 + threadIdx.x;   // 0..65535
    int r = ridx[idx];
#pragma unroll
    for (int h = 0; h < kH; h++)
        g_bias[h * 65536 + idx] = table[r * kH + h];
}

// ---------------------------------------------------------------------------
// QKV GEMM: y[m][j] = sum_c x[m][c]*W[j][c] + b[j], scattered into g_q/g_k/g_v
// M = 131072, Ncol = 384, K = 128 (full K per smem tile)
// grid (2048, 6), block 256, dyn smem 2*64*129*4 = 66048 B
// ---------------------------------------------------------------------------
__global__ __launch_bounds__(256) void qkv_gemm_kernel(
    const float* __restrict__ x, const float* __restrict__ w,
    const float* __restrict__ bias)
{
    extern __shared__ float smem[];
    float (*Xs)[129] = (float (*)[129])smem;
    float (*Ws)[129] = (float (*)[129])(smem + 64 * 129);

    int tid = threadIdx.x;
    int m0 = blockIdx.x * 64;
    int j0 = blockIdx.y * 64;

#pragma unroll
    for (int i = 0; i < 8; i++) {
        int l = tid + 256 * i;          // 0..2047
        int r = l >> 5, c4 = l & 31;
        float4 xv = *(const float4*)(x + (size_t)(m0 + r) * kC + c4 * 4);
        Xs[r][c4 * 4 + 0] = xv.x; Xs[r][c4 * 4 + 1] = xv.y;
        Xs[r][c4 * 4 + 2] = xv.z; Xs[r][c4 * 4 + 3] = xv.w;
        float4 wv = *(const float4*)(w + (size_t)(j0 + r) * kC + c4 * 4);
        Ws[r][c4 * 4 + 0] = wv.x; Ws[r][c4 * 4 + 1] = wv.y;
        Ws[r][c4 * 4 + 2] = wv.z; Ws[r][c4 * 4 + 3] = wv.w;
    }
    __syncthreads();

    int tx = tid & 15, ty = tid >> 4;
    float acc[4][4];
#pragma unroll
    for (int i = 0; i < 4; i++)
#pragma unroll
        for (int j = 0; j < 4; j++) acc[i][j] = 0.f;

#pragma unroll 8
    for (int kk = 0; kk < 128; kk++) {
        float a[4], bf[4];
#pragma unroll
        for (int i = 0; i < 4; i++) a[i] = Xs[ty * 4 + i][kk];
#pragma unroll
        for (int j = 0; j < 4; j++) bf[j] = Ws[tx * 4 + j][kk];
#pragma unroll
        for (int i = 0; i < 4; i++)
#pragma unroll
            for (int j = 0; j < 4; j++) acc[i][j] += a[i] * bf[j];
    }

    // Scatter epilogue: j = j0 + tx*4 .. +3 never straddles a 32/128 boundary
    int j = j0 + tx * 4;
    int part = j >> 7;           // 0=q 1=k 2=v
    int rem = j & 127;
    int h = rem >> 5, d = rem & 31;
    float* dst = (part == 0) ? g_q : ((part == 1) ? g_k : g_v);
    float b0 = bias[j], b1 = bias[j + 1], b2 = bias[j + 2], b3 = bias[j + 3];
#pragma unroll
    for (int i = 0; i < 4; i++) {
        int m = m0 + ty * 4 + i;
        int bidx = m >> 8, n = m & 255;
        float4 o;
        o.x = acc[i][0] + b0; o.y = acc[i][1] + b1;
        o.z = acc[i][2] + b2; o.w = acc[i][3] + b3;
        *(float4*)(dst + ((size_t)((bidx * kH + h) * kN + n)) * kHD + d) = o;
    }
}

// ---------------------------------------------------------------------------
// Proj GEMM: out[m][j] = sum_c ao[m][c]*Wp[j][c] + bp[j]
// grid (2048, 2), block 256, dyn smem 66048 B
// ---------------------------------------------------------------------------
__global__ __launch_bounds__(256) void proj_gemm_kernel(
    const float* __restrict__ w, const float* __restrict__ bias,
    float* __restrict__ out)
{
    extern __shared__ float smem[];
    float (*Xs)[129] = (float (*)[129])smem;
    float (*Ws)[129] = (float (*)[129])(smem + 64 * 129);

    int tid = threadIdx.x;
    int m0 = blockIdx.x * 64;
    int j0 = blockIdx.y * 64;
    const float* a = g_ao;

#pragma unroll
    for (int i = 0; i < 8; i++) {
        int l = tid + 256 * i;
        int r = l >> 5, c4 = l & 31;
        float4 xv = *(const float4*)(a + (size_t)(m0 + r) * kC + c4 * 4);
        Xs[r][c4 * 4 + 0] = xv.x; Xs[r][c4 * 4 + 1] = xv.y;
        Xs[r][c4 * 4 + 2] = xv.z; Xs[r][c4 * 4 + 3] = xv.w;
        float4 wv = *(const float4*)(w + (size_t)(j0 + r) * kC + c4 * 4);
        Ws[r][c4 * 4 + 0] = wv.x; Ws[r][c4 * 4 + 1] = wv.y;
        Ws[r][c4 * 4 + 2] = wv.z; Ws[r][c4 * 4 + 3] = wv.w;
    }
    __syncthreads();

    int tx = tid & 15, ty = tid >> 4;
    float acc[4][4];
#pragma unroll
    for (int i = 0; i < 4; i++)
#pragma unroll
        for (int j = 0; j < 4; j++) acc[i][j] = 0.f;

#pragma unroll 8
    for (int kk = 0; kk < 128; kk++) {
        float av[4], bf[4];
#pragma unroll
        for (int i = 0; i < 4; i++) av[i] = Xs[ty * 4 + i][kk];
#pragma unroll
        for (int j = 0; j < 4; j++) bf[j] = Ws[tx * 4 + j][kk];
#pragma unroll
        for (int i = 0; i < 4; i++)
#pragma unroll
            for (int j = 0; j < 4; j++) acc[i][j] += av[i] * bf[j];
    }

    int j = j0 + tx * 4;
    float b0 = bias[j], b1 = bias[j + 1], b2 = bias[j + 2], b3 = bias[j + 3];
#pragma unroll
    for (int i = 0; i < 4; i++) {
        int m = m0 + ty * 4 + i;
        float4 o;
        o.x = acc[i][0] + b0; o.y = acc[i][1] + b1;
        o.z = acc[i][2] + b2; o.w = acc[i][3] + b3;
        *(float4*)(out + (size_t)m * kC + j) = o;
    }
}

// ---------------------------------------------------------------------------
// Attention: one block per (b,h). K,V resident in smem. One thread per query
// row, online softmax. bias+mask staged per 64-m chunk in TRANSPOSED smem
// (bm[mc][n], pad 257) so the inner read bm[mc*257+t] is conflict-free.
// dyn smem = (8192 + 8192 + 64*257) * 4 = 131328 B
// ---------------------------------------------------------------------------
#define MCHUNK 64
__global__ __launch_bounds__(256) void attn_kernel(const float* __restrict__ mask)
{
    extern __shared__ float sm[];
    float* Ks = sm;                 // 256*32
    float* Vs = sm + 8192;          // 256*32
    float* bm = sm + 16384;         // 64*257

    int t = threadIdx.x;            // query row
    int bh = blockIdx.x;            // b*4 + h
    int b = bh >> 2, h = bh & 3;
    int w = b & (kNW - 1);

    const float* kptr = g_k + (size_t)bh * kN * kHD;
    const float* vptr = g_v + (size_t)bh * kN * kHD;
#pragma unroll
    for (int i = 0; i < 8; i++) {
        int l = t + 256 * i;        // 0..2047 float4s
        ((float4*)Ks)[l] = ((const float4*)kptr)[l];
        ((float4*)Vs)[l] = ((const float4*)vptr)[l];
    }

    const float scale = 0.17677669529663688f;  // 32^-0.5
    float qv[32];
    {
        const float* qptr = g_q + ((size_t)bh * kN + t) * kHD;
#pragma unroll
        for (int i = 0; i < 8; i++) {
            float4 qq = ((const float4*)qptr)[i];
            qv[4 * i + 0] = qq.x * scale; qv[4 * i + 1] = qq.y * scale;
            qv[4 * i + 2] = qq.z * scale; qv[4 * i + 3] = qq.w * scale;
        }
    }

    float o[32];
#pragma unroll
    for (int i = 0; i < 32; i++) o[i] = 0.f;
    float mx = -1e30f, ls = 0.f;

    const float* bias_h = g_bias + (size_t)h * 65536;
    const float* mask_w = mask + (size_t)w * 65536;

    for (int m0 = 0; m0 < kN; m0 += MCHUNK) {
        __syncthreads();
        // stage combined bias+mask chunk, transposed
#pragma unroll
        for (int it = 0; it < 16; it++) {
            int l = t + 256 * it;        // 0..4095
            int mc4 = l & 15, r = l >> 4;  // r: 0..255
            float4 bv = *(const float4*)(bias_h + r * 256 + m0 + mc4 * 4);
            float4 mv = *(const float4*)(mask_w + r * 256 + m0 + mc4 * 4);
            bm[(mc4 * 4 + 0) * 257 + r] = bv.x + mv.x;
            bm[(mc4 * 4 + 1) * 257 + r] = bv.y + mv.y;
            bm[(mc4 * 4 + 2) * 257 + r] = bv.z + mv.z;
            bm[(mc4 * 4 + 3) * 257 + r] = bv.w + mv.w;
        }
        __syncthreads();

#pragma unroll 2
        for (int mc = 0; mc < MCHUNK; mc++) {
            int m = m0 + mc;
            const float* krow = Ks + m * 32;
            float s0 = 0.f, s1 = 0.f, s2 = 0.f, s3 = 0.f;
#pragma unroll
            for (int d4 = 0; d4 < 8; d4++) {
                float4 kk = ((const float4*)krow)[d4];
                s0 += qv[d4 * 4 + 0] * kk.x;
                s1 += qv[d4 * 4 + 1] * kk.y;
                s2 += qv[d4 * 4 + 2] * kk.z;
                s3 += qv[d4 * 4 + 3] * kk.w;
            }
            float s = (s0 + s1) + (s2 + s3) + bm[mc * 257 + t];

            if (s > mx) {   // rare after the first few iterations
                float corr = __expf(mx - s);   // first iter: exp(-inf)=0
                ls *= corr;
#pragma unroll
                for (int i = 0; i < 32; i++) o[i] *= corr;
                mx = s;
            }
            float p = __expf(s - mx);
            ls += p;
            const float* vrow = Vs + m * 32;
#pragma unroll
            for (int d4 = 0; d4 < 8; d4++) {
                float4 vv = ((const float4*)vrow)[d4];
                o[d4 * 4 + 0] += p * vv.x;
                o[d4 * 4 + 1] += p * vv.y;
                o[d4 * 4 + 2] += p * vv.z;
                o[d4 * 4 + 3] += p * vv.w;
            }
        }
    }

    float inv = 1.f / ls;
    float* optr = g_ao + ((size_t)b * kN + t) * kC + h * kHD;
#pragma unroll
    for (int i = 0; i < 8; i++) {
        float4 ov;
        ov.x = o[4 * i + 0] * inv; ov.y = o[4 * i + 1] * inv;
        ov.z = o[4 * i + 2] * inv; ov.w = o[4 * i + 3] * inv;
        ((float4*)optr)[i] = ov;
    }
}

// ---------------------------------------------------------------------------
extern "C" void kernel_launch(void* const* d_in, const int* in_sizes, int n_in,
                              void* d_out, int out_size)
{
    const float* x      = (const float*)d_in[0];
    const float* mask   = (const float*)d_in[1];
    const float* qkv_w  = (const float*)d_in[2];
    const float* qkv_b  = (const float*)d_in[3];
    const float* proj_w = (const float*)d_in[4];
    const float* proj_b = (const float*)d_in[5];
    const float* table  = (const float*)d_in[6];
    const int*   ridx   = (const int*)d_in[7];
    float* out = (float*)d_out;

    (void)in_sizes; (void)n_in; (void)out_size;

    cudaFuncSetAttribute((const void*)qkv_gemm_kernel,
                         cudaFuncAttributeMaxDynamicSharedMemorySize, 66048);
    cudaFuncSetAttribute((const void*)proj_gemm_kernel,
                         cudaFuncAttributeMaxDynamicSharedMemorySize, 66048);
    cudaFuncSetAttribute((const void*)attn_kernel,
                         cudaFuncAttributeMaxDynamicSharedMemorySize, 131328);

    bias_gather_kernel<<<256, 256>>>(table, ridx);
    qkv_gemm_kernel<<<dim3(2048, 6), 256, 66048>>>(x, qkv_w, qkv_b);
    attn_kernel<<<2048, 256, 131328>>>(mask);
    proj_gemm_kernel<<<dim3(2048, 2), 256, 66048>>>(proj_w, proj_b, out);
}

// round 3
// speedup vs baseline: 1.0017x; 1.0017x over previous
#include <cuda_runtime.h>
#include <math.h>

// Problem constants
#define kB   512
#define kN   256
#define kC   128
#define kH   4
#define kHD  32
#define kNW  64

// Scratch (device globals: no runtime allocation allowed)
__device__ __align__(16) float g_q[(size_t)kB * kH * kN * kHD];
__device__ __align__(16) float g_k[(size_t)kB * kH * kN * kHD];
__device__ __align__(16) float g_v[(size_t)kB * kH * kN * kHD];
__device__ __align__(16) float g_bias[(size_t)kH * kN * kN];
__device__ __align__(16) float g_ao[(size_t)kB * kN * kC];

// ---------------------------------------------------------------------------
// Bias gather: g_bias[h][n][m] = table[rel_idx[n*256+m]][h]
// ---------------------------------------------------------------------------
__global__ __launch_bounds__(256) void bias_gather_kernel(
    const float* __restrict__ table, const int* __restrict__ ridx)
{
    int idx = blockIdx.x * 256 + threadIdx.x;   // 0..65535
    int r = ridx[idx];
#pragma unroll
    for (int h = 0; h < kH; h++)
        g_bias[h * 65536 + idx] = table[r * kH + h];
}

// ---------------------------------------------------------------------------
// QKV GEMM: y[m][j] = sum_c x[m][c]*W[j][c] + b[j], scattered into g_q/g_k/g_v
// M = 131072, Ncol = 384, K = 128 (full K per smem tile)
// grid (2048, 6), block 256, dyn smem 2*64*129*4 = 66048 B
// ---------------------------------------------------------------------------
__global__ __launch_bounds__(256) void qkv_gemm_kernel(
    const float* __restrict__ x, const float* __restrict__ w,
    const float* __restrict__ bias)
{
    extern __shared__ float smem[];
    float (*Xs)[129] = (float (*)[129])smem;
    float (*Ws)[129] = (float (*)[129])(smem + 64 * 129);

    int tid = threadIdx.x;
    int m0 = blockIdx.x * 64;
    int j0 = blockIdx.y * 64;

#pragma unroll
    for (int i = 0; i < 8; i++) {
        int l = tid + 256 * i;          // 0..2047
        int r = l >> 5, c4 = l & 31;
        float4 xv = *(const float4*)(x + (size_t)(m0 + r) * kC + c4 * 4);
        Xs[r][c4 * 4 + 0] = xv.x; Xs[r][c4 * 4 + 1] = xv.y;
        Xs[r][c4 * 4 + 2] = xv.z; Xs[r][c4 * 4 + 3] = xv.w;
        float4 wv = *(const float4*)(w + (size_t)(j0 + r) * kC + c4 * 4);
        Ws[r][c4 * 4 + 0] = wv.x; Ws[r][c4 * 4 + 1] = wv.y;
        Ws[r][c4 * 4 + 2] = wv.z; Ws[r][c4 * 4 + 3] = wv.w;
    }
    __syncthreads();

    int tx = tid & 15, ty = tid >> 4;
    float acc[4][4];
#pragma unroll
    for (int i = 0; i < 4; i++)
#pragma unroll
        for (int j = 0; j < 4; j++) acc[i][j] = 0.f;

#pragma unroll 8
    for (int kk = 0; kk < 128; kk++) {
        float a[4], bf[4];
#pragma unroll
        for (int i = 0; i < 4; i++) a[i] = Xs[ty * 4 + i][kk];
#pragma unroll
        for (int j = 0; j < 4; j++) bf[j] = Ws[tx * 4 + j][kk];
#pragma unroll
        for (int i = 0; i < 4; i++)
#pragma unroll
            for (int j = 0; j < 4; j++) acc[i][j] += a[i] * bf[j];
    }

    // Scatter epilogue: j = j0 + tx*4 .. +3 never straddles a 32/128 boundary
    int j = j0 + tx * 4;
    int part = j >> 7;           // 0=q 1=k 2=v
    int rem = j & 127;
    int h = rem >> 5, d = rem & 31;
    float* dst = (part == 0) ? g_q : ((part == 1) ? g_k : g_v);
    float b0 = bias[j], b1 = bias[j + 1], b2 = bias[j + 2], b3 = bias[j + 3];
#pragma unroll
    for (int i = 0; i < 4; i++) {
        int m = m0 + ty * 4 + i;
        int bidx = m >> 8, n = m & 255;
        float4 o;
        o.x = acc[i][0] + b0; o.y = acc[i][1] + b1;
        o.z = acc[i][2] + b2; o.w = acc[i][3] + b3;
        *(float4*)(dst + ((size_t)((bidx * kH + h) * kN + n)) * kHD + d) = o;
    }
}

// ---------------------------------------------------------------------------
// Proj GEMM: out[m][j] = sum_c ao[m][c]*Wp[j][c] + bp[j]
// grid (2048, 2), block 256, dyn smem 66048 B
// ---------------------------------------------------------------------------
__global__ __launch_bounds__(256) void proj_gemm_kernel(
    const float* __restrict__ w, const float* __restrict__ bias,
    float* __restrict__ out)
{
    extern __shared__ float smem[];
    float (*Xs)[129] = (float (*)[129])smem;
    float (*Ws)[129] = (float (*)[129])(smem + 64 * 129);

    int tid = threadIdx.x;
    int m0 = blockIdx.x * 64;
    int j0 = blockIdx.y * 64;
    const float* a = g_ao;

#pragma unroll
    for (int i = 0; i < 8; i++) {
        int l = tid + 256 * i;
        int r = l >> 5, c4 = l & 31;
        float4 xv = *(const float4*)(a + (size_t)(m0 + r) * kC + c4 * 4);
        Xs[r][c4 * 4 + 0] = xv.x; Xs[r][c4 * 4 + 1] = xv.y;
        Xs[r][c4 * 4 + 2] = xv.z; Xs[r][c4 * 4 + 3] = xv.w;
        float4 wv = *(const float4*)(w + (size_t)(j0 + r) * kC + c4 * 4);
        Ws[r][c4 * 4 + 0] = wv.x; Ws[r][c4 * 4 + 1] = wv.y;
        Ws[r][c4 * 4 + 2] = wv.z; Ws[r][c4 * 4 + 3] = wv.w;
    }
    __syncthreads();

    int tx = tid & 15, ty = tid >> 4;
    float acc[4][4];
#pragma unroll
    for (int i = 0; i < 4; i++)
#pragma unroll
        for (int j = 0; j < 4; j++) acc[i][j] = 0.f;

#pragma unroll 8
    for (int kk = 0; kk < 128; kk++) {
        float av[4], bf[4];
#pragma unroll
        for (int i = 0; i < 4; i++) av[i] = Xs[ty * 4 + i][kk];
#pragma unroll
        for (int j = 0; j < 4; j++) bf[j] = Ws[tx * 4 + j][kk];
#pragma unroll
        for (int i = 0; i < 4; i++)
#pragma unroll
            for (int j = 0; j < 4; j++) acc[i][j] += av[i] * bf[j];
    }

    int j = j0 + tx * 4;
    float b0 = bias[j], b1 = bias[j + 1], b2 = bias[j + 2], b3 = bias[j + 3];
#pragma unroll
    for (int i = 0; i < 4; i++) {
        int m = m0 + ty * 4 + i;
        float4 o;
        o.x = acc[i][0] + b0; o.y = acc[i][1] + b1;
        o.z = acc[i][2] + b2; o.w = acc[i][3] + b3;
        *(float4*)(out + (size_t)m * kC + j) = o;
    }
}

// ---------------------------------------------------------------------------
// Attention: one block per (b,h). K,V resident in smem. One thread per query
// row, online softmax. bias+mask staged per 64-m chunk in TRANSPOSED smem
// (bm[mc][n], pad 257) so the inner read bm[mc*257+t] is conflict-free.
// dyn smem = (8192 + 8192 + 64*257) * 4 = 131328 B
// ---------------------------------------------------------------------------
#define MCHUNK 64
__global__ __launch_bounds__(256) void attn_kernel(const float* __restrict__ mask)
{
    extern __shared__ float sm[];
    float* Ks = sm;                 // 256*32
    float* Vs = sm + 8192;          // 256*32
    float* bm = sm + 16384;         // 64*257

    int t = threadIdx.x;            // query row
    int bh = blockIdx.x;            // b*4 + h
    int b = bh >> 2, h = bh & 3;
    int w = b & (kNW - 1);

    const float* kptr = g_k + (size_t)bh * kN * kHD;
    const float* vptr = g_v + (size_t)bh * kN * kHD;
#pragma unroll
    for (int i = 0; i < 8; i++) {
        int l = t + 256 * i;        // 0..2047 float4s
        ((float4*)Ks)[l] = ((const float4*)kptr)[l];
        ((float4*)Vs)[l] = ((const float4*)vptr)[l];
    }

    const float scale = 0.17677669529663688f;  // 32^-0.5
    float qv[32];
    {
        const float* qptr = g_q + ((size_t)bh * kN + t) * kHD;
#pragma unroll
        for (int i = 0; i < 8; i++) {
            float4 qq = ((const float4*)qptr)[i];
            qv[4 * i + 0] = qq.x * scale; qv[4 * i + 1] = qq.y * scale;
            qv[4 * i + 2] = qq.z * scale; qv[4 * i + 3] = qq.w * scale;
        }
    }

    float o[32];
#pragma unroll
    for (int i = 0; i < 32; i++) o[i] = 0.f;
    float mx = -1e30f, ls = 0.f;

    const float* bias_h = g_bias + (size_t)h * 65536;
    const float* mask_w = mask + (size_t)w * 65536;

    for (int m0 = 0; m0 < kN; m0 += MCHUNK) {
        __syncthreads();
        // stage combined bias+mask chunk, transposed
#pragma unroll
        for (int it = 0; it < 16; it++) {
            int l = t + 256 * it;        // 0..4095
            int mc4 = l & 15, r = l >> 4;  // r: 0..255
            float4 bv = *(const float4*)(bias_h + r * 256 + m0 + mc4 * 4);
            float4 mv = *(const float4*)(mask_w + r * 256 + m0 + mc4 * 4);
            bm[(mc4 * 4 + 0) * 257 + r] = bv.x + mv.x;
            bm[(mc4 * 4 + 1) * 257 + r] = bv.y + mv.y;
            bm[(mc4 * 4 + 2) * 257 + r] = bv.z + mv.z;
            bm[(mc4 * 4 + 3) * 257 + r] = bv.w + mv.w;
        }
        __syncthreads();

#pragma unroll 2
        for (int mc = 0; mc < MCHUNK; mc++) {
            int m = m0 + mc;
            const float* krow = Ks + m * 32;
            float s0 = 0.f, s1 = 0.f, s2 = 0.f, s3 = 0.f;
#pragma unroll
            for (int d4 = 0; d4 < 8; d4++) {
                float4 kk = ((const float4*)krow)[d4];
                s0 += qv[d4 * 4 + 0] * kk.x;
                s1 += qv[d4 * 4 + 1] * kk.y;
                s2 += qv[d4 * 4 + 2] * kk.z;
                s3 += qv[d4 * 4 + 3] * kk.w;
            }
            float s = (s0 + s1) + (s2 + s3) + bm[mc * 257 + t];

            if (s > mx) {   // rare after the first few iterations
                float corr = __expf(mx - s);   // first iter: exp(-inf)=0
                ls *= corr;
#pragma unroll
                for (int i = 0; i < 32; i++) o[i] *= corr;
                mx = s;
            }
            float p = __expf(s - mx);
            ls += p;
            const float* vrow = Vs + m * 32;
#pragma unroll
            for (int d4 = 0; d4 < 8; d4++) {
                float4 vv = ((const float4*)vrow)[d4];
                o[d4 * 4 + 0] += p * vv.x;
                o[d4 * 4 + 1] += p * vv.y;
                o[d4 * 4 + 2] += p * vv.z;
                o[d4 * 4 + 3] += p * vv.w;
            }
        }
    }

    float inv = 1.f / ls;
    float* optr = g_ao + ((size_t)b * kN + t) * kC + h * kHD;
#pragma unroll
    for (int i = 0; i < 8; i++) {
        float4 ov;
        ov.x = o[4 * i + 0] * inv; ov.y = o[4 * i + 1] * inv;
        ov.z = o[4 * i + 2] * inv; ov.w = o[4 * i + 3] * inv;
        ((float4*)optr)[i] = ov;
    }
}

// ---------------------------------------------------------------------------
extern "C" void kernel_launch(void* const* d_in, const int* in_sizes, int n_in,
                              void* d_out, int out_size)
{
    const float* x      = (const float*)d_in[0];
    const float* mask   = (const float*)d_in[1];
    const float* qkv_w  = (const float*)d_in[2];
    const float* qkv_b  = (const float*)d_in[3];
    const float* proj_w = (const float*)d_in[4];
    const float* proj_b = (const float*)d_in[5];
    const float* table  = (const float*)d_in[6];
    const int*   ridx   = (const int*)d_in[7];
    float* out = (float*)d_out;

    (void)in_sizes; (void)n_in; (void)out_size;

    cudaFuncSetAttribute((const void*)qkv_gemm_kernel,
                         cudaFuncAttributeMaxDynamicSharedMemorySize, 66048);
    cudaFuncSetAttribute((const void*)proj_gemm_kernel,
                         cudaFuncAttributeMaxDynamicSharedMemorySize, 66048);
    cudaFuncSetAttribute((const void*)attn_kernel,
                         cudaFuncAttributeMaxDynamicSharedMemorySize, 131328);

    bias_gather_kernel<<<256, 256>>>(table, ridx);
    qkv_gemm_kernel<<<dim3(2048, 6), 256, 66048>>>(x, qkv_w, qkv_b);
    attn_kernel<<<2048, 256, 131328>>>(mask);
    proj_gemm_kernel<<<dim3(2048, 2), 256, 66048>>>(proj_w, proj_b, out);
}

// round 4
// speedup vs baseline: 1.3661x; 1.3638x over previous
#include <cuda_runtime.h>
#include <math.h>

// Problem constants
#define kB   512
#define kN   256
#define kC   128
#define kH   4
#define kHD  32
#define kNW  64

// Scratch (device globals: no runtime allocation allowed)
__device__ __align__(16) float g_q[(size_t)kB * kH * kN * kHD];
__device__ __align__(16) float g_k[(size_t)kB * kH * kN * kHD];
__device__ __align__(16) float g_v[(size_t)kB * kH * kN * kHD];
__device__ __align__(16) float g_bias[(size_t)kH * kN * kN];
__device__ __align__(16) float g_ao[(size_t)kB * kN * kC];

// ---------------------------------------------------------------------------
// Bias gather: g_bias[h][n][m] = table[rel_idx[n*256+m]][h]
// ---------------------------------------------------------------------------
__global__ __launch_bounds__(256) void bias_gather_kernel(
    const float* __restrict__ table, const int* __restrict__ ridx)
{
    int idx = blockIdx.x * 256 + threadIdx.x;   // 0..65535
    int r = ridx[idx];
#pragma unroll
    for (int h = 0; h < kH; h++)
        g_bias[h * 65536 + idx] = table[r * kH + h];
}

// ---------------------------------------------------------------------------
// SGEMM core: C[128m x 128n] tile, 256 threads, 8x8 per thread, K=128 in
// 16 chunks of 8, double-buffered smem, register prefetch.
// A: [M x 128] row-major, B: [Ncol x 128] row-major (we compute A @ B^T).
// ---------------------------------------------------------------------------
struct GemmAcc {
    float acc[8][8];
};

__device__ __forceinline__ void sgemm128_body(
    const float* __restrict__ A, const float* __restrict__ B,
    int m0, int j0, GemmAcc& R)
{
    __shared__ float As[2][8][132];
    __shared__ float Bs[2][8][132];

    int tid = threadIdx.x;
    int f4row = tid >> 1;          // 0..127
    int f4half = tid & 1;          // which float4 of the 8-wide k chunk

    const float* aptr = A + (size_t)(m0 + f4row) * kC + f4half * 4;
    const float* bptr = B + (size_t)(j0 + f4row) * kC + f4half * 4;

    int row0 = (tid >> 4) * 8;
    int col0 = (tid & 15) * 8;

#pragma unroll
    for (int i = 0; i < 8; i++)
#pragma unroll
        for (int j = 0; j < 8; j++) R.acc[i][j] = 0.f;

    // load chunk 0
    {
        float4 av = *(const float4*)(aptr);
        float4 bv = *(const float4*)(bptr);
        As[0][f4half * 4 + 0][f4row] = av.x; As[0][f4half * 4 + 1][f4row] = av.y;
        As[0][f4half * 4 + 2][f4row] = av.z; As[0][f4half * 4 + 3][f4row] = av.w;
        Bs[0][f4half * 4 + 0][f4row] = bv.x; Bs[0][f4half * 4 + 1][f4row] = bv.y;
        Bs[0][f4half * 4 + 2][f4row] = bv.z; Bs[0][f4half * 4 + 3][f4row] = bv.w;
    }
    __syncthreads();

#pragma unroll
    for (int kt = 0; kt < 16; kt++) {
        int cur = kt & 1;
        float4 av, bv;
        if (kt < 15) {
            av = *(const float4*)(aptr + (kt + 1) * 8);
            bv = *(const float4*)(bptr + (kt + 1) * 8);
        }
#pragma unroll
        for (int kk = 0; kk < 8; kk++) {
            float4 a0 = *(const float4*)(&As[cur][kk][row0]);
            float4 a1 = *(const float4*)(&As[cur][kk][row0 + 4]);
            float4 b0 = *(const float4*)(&Bs[cur][kk][col0]);
            float4 b1 = *(const float4*)(&Bs[cur][kk][col0 + 4]);
            float ar[8] = {a0.x, a0.y, a0.z, a0.w, a1.x, a1.y, a1.z, a1.w};
            float br[8] = {b0.x, b0.y, b0.z, b0.w, b1.x, b1.y, b1.z, b1.w};
#pragma unroll
            for (int i = 0; i < 8; i++)
#pragma unroll
                for (int j = 0; j < 8; j++) R.acc[i][j] += ar[i] * br[j];
        }
        if (kt < 15) {
            int nxt = cur ^ 1;
            As[nxt][f4half * 4 + 0][f4row] = av.x; As[nxt][f4half * 4 + 1][f4row] = av.y;
            As[nxt][f4half * 4 + 2][f4row] = av.z; As[nxt][f4half * 4 + 3][f4row] = av.w;
            Bs[nxt][f4half * 4 + 0][f4row] = bv.x; Bs[nxt][f4half * 4 + 1][f4row] = bv.y;
            Bs[nxt][f4half * 4 + 2][f4row] = bv.z; Bs[nxt][f4half * 4 + 3][f4row] = bv.w;
            __syncthreads();
        }
    }
}

// ---------------------------------------------------------------------------
// QKV GEMM: grid (1024, 3), block 256. blockIdx.y selects q/k/v exactly.
// Scatter into g_q/g_k/g_v [b][h][n][d].
// ---------------------------------------------------------------------------
__global__ __launch_bounds__(256) void qkv_gemm_kernel(
    const float* __restrict__ x, const float* __restrict__ w,
    const float* __restrict__ bias)
{
    int m0 = blockIdx.x * 128;
    int part = blockIdx.y;              // 0=q 1=k 2=v
    int j0 = part * 128;

    GemmAcc R;
    sgemm128_body(x, w, m0, j0, R);

    int tid = threadIdx.x;
    int row0 = (tid >> 4) * 8;
    int col0 = (tid & 15) * 8;          // 8-aligned -> stays within one head
    int h = col0 >> 5, d = col0 & 31;
    float* dst = (part == 0) ? g_q : ((part == 1) ? g_k : g_v);

    float bb[8];
#pragma unroll
    for (int j = 0; j < 8; j++) bb[j] = bias[j0 + col0 + j];

#pragma unroll
    for (int i = 0; i < 8; i++) {
        int m = m0 + row0 + i;
        int bidx = m >> 8, n = m & 255;
        float* p = dst + ((size_t)((bidx * kH + h) * kN + n)) * kHD + d;
        float4 o0, o1;
        o0.x = R.acc[i][0] + bb[0]; o0.y = R.acc[i][1] + bb[1];
        o0.z = R.acc[i][2] + bb[2]; o0.w = R.acc[i][3] + bb[3];
        o1.x = R.acc[i][4] + bb[4]; o1.y = R.acc[i][5] + bb[5];
        o1.z = R.acc[i][6] + bb[6]; o1.w = R.acc[i][7] + bb[7];
        *(float4*)(p) = o0;
        *(float4*)(p + 4) = o1;
    }
}

// ---------------------------------------------------------------------------
// Proj GEMM: grid (1024, 1), block 256. out[m][j]
// ---------------------------------------------------------------------------
__global__ __launch_bounds__(256) void proj_gemm_kernel(
    const float* __restrict__ w, const float* __restrict__ bias,
    float* __restrict__ out)
{
    int m0 = blockIdx.x * 128;

    GemmAcc R;
    sgemm128_body(g_ao, w, m0, 0, R);

    int tid = threadIdx.x;
    int row0 = (tid >> 4) * 8;
    int col0 = (tid & 15) * 8;

    float bb[8];
#pragma unroll
    for (int j = 0; j < 8; j++) bb[j] = bias[col0 + j];

#pragma unroll
    for (int i = 0; i < 8; i++) {
        int m = m0 + row0 + i;
        float* p = out + (size_t)m * kC + col0;
        float4 o0, o1;
        o0.x = R.acc[i][0] + bb[0]; o0.y = R.acc[i][1] + bb[1];
        o0.z = R.acc[i][2] + bb[2]; o0.w = R.acc[i][3] + bb[3];
        o1.x = R.acc[i][4] + bb[4]; o1.y = R.acc[i][5] + bb[5];
        o1.z = R.acc[i][6] + bb[6]; o1.w = R.acc[i][7] + bb[7];
        *(float4*)(p) = o0;
        *(float4*)(p + 4) = o1;
    }
}

// ---------------------------------------------------------------------------
// Attention: one block per (b,h). K,V resident in smem. One thread per query
// row. NO max-subtraction: scores are bounded (~|s|<20), exp(s) is safe in
// fp32 and softmax is shift-invariant, so skip online-max entirely.
// bias+mask staged per 32-m chunk, transposed (bm[mc][n], pad 257).
// dyn smem = (16384 + 32*257)*4 = 98432 B  -> 2 blocks/SM.
// ---------------------------------------------------------------------------
#define MCHUNK 32
__global__ __launch_bounds__(256) void attn_kernel(const float* __restrict__ mask)
{
    extern __shared__ float sm[];
    float* Ks = sm;                 // 256*32
    float* Vs = sm + 8192;          // 256*32
    float* bm = sm + 16384;         // 32*257

    int t = threadIdx.x;            // query row
    int bh = blockIdx.x;            // b*4 + h
    int b = bh >> 2, h = bh & 3;
    int w = b & (kNW - 1);

    const float* kptr = g_k + (size_t)bh * kN * kHD;
    const float* vptr = g_v + (size_t)bh * kN * kHD;
#pragma unroll
    for (int i = 0; i < 8; i++) {
        int l = t + 256 * i;        // 0..2047 float4s
        ((float4*)Ks)[l] = ((const float4*)kptr)[l];
        ((float4*)Vs)[l] = ((const float4*)vptr)[l];
    }

    const float scale = 0.17677669529663688f;  // 32^-0.5
    float qv[32];
    {
        const float* qptr = g_q + ((size_t)bh * kN + t) * kHD;
#pragma unroll
        for (int i = 0; i < 8; i++) {
            float4 qq = ((const float4*)qptr)[i];
            qv[4 * i + 0] = qq.x * scale; qv[4 * i + 1] = qq.y * scale;
            qv[4 * i + 2] = qq.z * scale; qv[4 * i + 3] = qq.w * scale;
        }
    }

    float o[32];
#pragma unroll
    for (int i = 0; i < 32; i++) o[i] = 0.f;
    float ls = 0.f;

    const float* bias_h = g_bias + (size_t)h * 65536;
    const float* mask_w = mask + (size_t)w * 65536;

    for (int m0 = 0; m0 < kN; m0 += MCHUNK) {
        __syncthreads();
        // stage combined bias+mask chunk, transposed: bm[mc][n]
#pragma unroll
        for (int it = 0; it < 8; it++) {
            int l = t + 256 * it;          // 0..2047
            int mc4 = l & 7, r = l >> 3;   // r: 0..255
            float4 bv = *(const float4*)(bias_h + r * 256 + m0 + mc4 * 4);
            float4 mv = *(const float4*)(mask_w + r * 256 + m0 + mc4 * 4);
            bm[(mc4 * 4 + 0) * 257 + r] = bv.x + mv.x;
            bm[(mc4 * 4 + 1) * 257 + r] = bv.y + mv.y;
            bm[(mc4 * 4 + 2) * 257 + r] = bv.z + mv.z;
            bm[(mc4 * 4 + 3) * 257 + r] = bv.w + mv.w;
        }
        __syncthreads();

#pragma unroll 4
        for (int mc = 0; mc < MCHUNK; mc++) {
            int m = m0 + mc;
            const float* krow = Ks + m * 32;
            float s0 = 0.f, s1 = 0.f, s2 = 0.f, s3 = 0.f;
#pragma unroll
            for (int d4 = 0; d4 < 8; d4++) {
                float4 kk = ((const float4*)krow)[d4];
                s0 += qv[d4 * 4 + 0] * kk.x;
                s1 += qv[d4 * 4 + 1] * kk.y;
                s2 += qv[d4 * 4 + 2] * kk.z;
                s3 += qv[d4 * 4 + 3] * kk.w;
            }
            float s = (s0 + s1) + (s2 + s3) + bm[mc * 257 + t];
            float p = __expf(s);
            ls += p;
            const float* vrow = Vs + m * 32;
#pragma unroll
            for (int d4 = 0; d4 < 8; d4++) {
                float4 vv = ((const float4*)vrow)[d4];
                o[d4 * 4 + 0] += p * vv.x;
                o[d4 * 4 + 1] += p * vv.y;
                o[d4 * 4 + 2] += p * vv.z;
                o[d4 * 4 + 3] += p * vv.w;
            }
        }
    }

    float inv = 1.f / ls;
    float* optr = g_ao + ((size_t)b * kN + t) * kC + h * kHD;
#pragma unroll
    for (int i = 0; i < 8; i++) {
        float4 ov;
        ov.x = o[4 * i + 0] * inv; ov.y = o[4 * i + 1] * inv;
        ov.z = o[4 * i + 2] * inv; ov.w = o[4 * i + 3] * inv;
        ((float4*)optr)[i] = ov;
    }
}

// ---------------------------------------------------------------------------
extern "C" void kernel_launch(void* const* d_in, const int* in_sizes, int n_in,
                              void* d_out, int out_size)
{
    const float* x      = (const float*)d_in[0];
    const float* mask   = (const float*)d_in[1];
    const float* qkv_w  = (const float*)d_in[2];
    const float* qkv_b  = (const float*)d_in[3];
    const float* proj_w = (const float*)d_in[4];
    const float* proj_b = (const float*)d_in[5];
    const float* table  = (const float*)d_in[6];
    const int*   ridx   = (const int*)d_in[7];
    float* out = (float*)d_out;

    (void)in_sizes; (void)n_in; (void)out_size;

    cudaFuncSetAttribute((const void*)attn_kernel,
                         cudaFuncAttributeMaxDynamicSharedMemorySize, 98432);

    bias_gather_kernel<<<256, 256>>>(table, ridx);
    qkv_gemm_kernel<<<dim3(1024, 3), 256>>>(x, qkv_w, qkv_b);
    attn_kernel<<<2048, 256, 98432>>>(mask);
    proj_gemm_kernel<<<1024, 256>>>(proj_w, proj_b, out);
}

// round 5
// speedup vs baseline: 1.8176x; 1.3305x over previous
#include <cuda_runtime.h>
#include <math.h>
#include <stdint.h>

// Problem constants
#define kB   512
#define kN   256
#define kC   128
#define kH   4
#define kHD  32
#define kNW  64

// Scratch (device globals: no runtime allocation allowed)
__device__ __align__(16) float g_q[(size_t)kB * kH * kN * kHD];
__device__ __align__(16) float g_k[(size_t)kB * kH * kN * kHD];
__device__ __align__(16) float g_v[(size_t)kB * kH * kN * kHD];
__device__ __align__(16) float g_bias[(size_t)kH * kN * kN];
__device__ __align__(16) float g_ao[(size_t)kB * kN * kC];

// ---------------------------------------------------------------------------
// Bias gather: g_bias[h][n][m] = table[rel_idx[n*256+m]][h]
// ---------------------------------------------------------------------------
__global__ __launch_bounds__(256) void bias_gather_kernel(
    const float* __restrict__ table, const int* __restrict__ ridx)
{
    int idx = blockIdx.x * 256 + threadIdx.x;   // 0..65535
    int r = ridx[idx];
#pragma unroll
    for (int h = 0; h < kH; h++)
        g_bias[h * 65536 + idx] = table[r * kH + h];
}

// ---------------------------------------------------------------------------
// TF32 helpers
// ---------------------------------------------------------------------------
__device__ __forceinline__ uint32_t f2tf32(float f) {
    uint32_t u;
    asm("cvt.rna.tf32.f32 %0, %1;" : "=r"(u) : "f"(f));
    return u;
}

__device__ __forceinline__ void mma_tf32(
    float& c0, float& c1, float& c2, float& c3,
    uint32_t a0, uint32_t a1, uint32_t a2, uint32_t a3,
    uint32_t b0, uint32_t b1)
{
    asm volatile(
        "mma.sync.aligned.m16n8k8.row.col.f32.tf32.tf32.f32 "
        "{%0,%1,%2,%3}, {%4,%5,%6,%7}, {%8,%9}, {%0,%1,%2,%3};"
        : "+f"(c0), "+f"(c1), "+f"(c2), "+f"(c3)
        : "r"(a0), "r"(a1), "r"(a2), "r"(a3), "r"(b0), "r"(b1));
}

// ---------------------------------------------------------------------------
// TF32 MMA GEMM body: C[128m x 128n] per block, computes A @ B^T.
// A: [M x 128] row-major fp32; B: [Ncol x 128] row-major fp32 (row = out col).
// 256 threads = 8 warps; warp (wm, wn) covers rows wm*64..+63, cols wn*32..+31
// via 4x4 grid of m16n8k8 MMAs. K = 128 in 4 chunks of 32, double-buffered.
// Dyn smem: As[2][128][36] + Bs[2][128][36] uint32 = 73728 B.
// ---------------------------------------------------------------------------
#define GBK 32
#define GPAD 36

struct MmaAcc { float c[4][4][4]; };   // [mi][ni][frag]

__device__ __forceinline__ void mma_gemm_body(
    const float* __restrict__ A, const float* __restrict__ B,
    int m0, MmaAcc& R)
{
    extern __shared__ uint32_t smem_u[];
    uint32_t (*As)[128][GPAD] = (uint32_t (*)[128][GPAD])smem_u;
    uint32_t (*Bs)[128][GPAD] = (uint32_t (*)[128][GPAD])(smem_u + 2 * 128 * GPAD);

    int tid = threadIdx.x;
    int lane = tid & 31;
    int wid = tid >> 5;
    int wm = wid & 1;          // 0..1
    int wn = wid >> 1;         // 0..3

    int lrow = tid >> 1;              // 0..127
    int lcol = (tid & 1) * 16;        // 0 or 16 (floats within 32-float chunk)

    const float* aptr = A + (size_t)(m0 + lrow) * kC + lcol;
    const float* bptr = B + (size_t)lrow * kC + lcol;

#pragma unroll
    for (int mi = 0; mi < 4; mi++)
#pragma unroll
        for (int ni = 0; ni < 4; ni++)
#pragma unroll
            for (int f = 0; f < 4; f++) R.c[mi][ni][f] = 0.f;

    // stage chunk 0
    {
#pragma unroll
        for (int i = 0; i < 4; i++) {
            float4 av = *(const float4*)(aptr + i * 4);
            float4 bv = *(const float4*)(bptr + i * 4);
            As[0][lrow][lcol + i * 4 + 0] = f2tf32(av.x);
            As[0][lrow][lcol + i * 4 + 1] = f2tf32(av.y);
            As[0][lrow][lcol + i * 4 + 2] = f2tf32(av.z);
            As[0][lrow][lcol + i * 4 + 3] = f2tf32(av.w);
            Bs[0][lrow][lcol + i * 4 + 0] = f2tf32(bv.x);
            Bs[0][lrow][lcol + i * 4 + 1] = f2tf32(bv.y);
            Bs[0][lrow][lcol + i * 4 + 2] = f2tf32(bv.z);
            Bs[0][lrow][lcol + i * 4 + 3] = f2tf32(bv.w);
        }
    }
    __syncthreads();

    int qrow = lane >> 2;      // 0..7
    int qk = lane & 3;         // 0..3

#pragma unroll
    for (int kc = 0; kc < 4; kc++) {
        int cur = kc & 1;
        float4 av[4], bv[4];
        if (kc < 3) {
#pragma unroll
            for (int i = 0; i < 4; i++) {
                av[i] = *(const float4*)(aptr + (kc + 1) * GBK + i * 4);
                bv[i] = *(const float4*)(bptr + (kc + 1) * GBK + i * 4);
            }
        }

#pragma unroll
        for (int k8 = 0; k8 < 4; k8++) {
            int kb = k8 * 8 + qk;
            uint32_t af[4][4], bf[4][2];
#pragma unroll
            for (int mi = 0; mi < 4; mi++) {
                int r = wm * 64 + mi * 16 + qrow;
                af[mi][0] = As[cur][r][kb];
                af[mi][1] = As[cur][r + 8][kb];
                af[mi][2] = As[cur][r][kb + 4];
                af[mi][3] = As[cur][r + 8][kb + 4];
            }
#pragma unroll
            for (int ni = 0; ni < 4; ni++) {
                int r = wn * 32 + ni * 8 + qrow;
                bf[ni][0] = Bs[cur][r][kb];
                bf[ni][1] = Bs[cur][r][kb + 4];
            }
#pragma unroll
            for (int mi = 0; mi < 4; mi++)
#pragma unroll
                for (int ni = 0; ni < 4; ni++)
                    mma_tf32(R.c[mi][ni][0], R.c[mi][ni][1],
                             R.c[mi][ni][2], R.c[mi][ni][3],
                             af[mi][0], af[mi][1], af[mi][2], af[mi][3],
                             bf[ni][0], bf[ni][1]);
        }

        if (kc < 3) {
            int nxt = cur ^ 1;
#pragma unroll
            for (int i = 0; i < 4; i++) {
                As[nxt][lrow][lcol + i * 4 + 0] = f2tf32(av[i].x);
                As[nxt][lrow][lcol + i * 4 + 1] = f2tf32(av[i].y);
                As[nxt][lrow][lcol + i * 4 + 2] = f2tf32(av[i].z);
                As[nxt][lrow][lcol + i * 4 + 3] = f2tf32(av[i].w);
                Bs[nxt][lrow][lcol + i * 4 + 0] = f2tf32(bv[i].x);
                Bs[nxt][lrow][lcol + i * 4 + 1] = f2tf32(bv[i].y);
                Bs[nxt][lrow][lcol + i * 4 + 2] = f2tf32(bv[i].z);
                Bs[nxt][lrow][lcol + i * 4 + 3] = f2tf32(bv[i].w);
            }
            __syncthreads();
        }
    }
}

#define GEMM_SMEM (2 * 128 * GPAD * 2 * 4)   // 73728 B

// ---------------------------------------------------------------------------
// QKV GEMM: grid (1024, 3). blockIdx.y = part (q/k/v). Scatter to [b][h][n][d].
// ---------------------------------------------------------------------------
__global__ __launch_bounds__(256) void qkv_gemm_kernel(
    const float* __restrict__ x, const float* __restrict__ w,
    const float* __restrict__ bias)
{
    int m0 = blockIdx.x * 128;
    int part = blockIdx.y;
    int j0 = part * 128;

    MmaAcc R;
    mma_gemm_body(x, w + (size_t)j0 * kC, m0, R);

    int lane = threadIdx.x & 31;
    int wid = threadIdx.x >> 5;
    int wm = wid & 1, wn = wid >> 1;
    int h = wn;                               // col>>5 == wn since wn*32 base
    float* dst = (part == 0) ? g_q : ((part == 1) ? g_k : g_v);

#pragma unroll
    for (int ni = 0; ni < 4; ni++) {
        int col = wn * 32 + ni * 8 + 2 * (lane & 3);
        int d = col & 31;
        float b0 = bias[j0 + col], b1 = bias[j0 + col + 1];
#pragma unroll
        for (int mi = 0; mi < 4; mi++) {
#pragma unroll
            for (int half = 0; half < 2; half++) {
                int m = m0 + wm * 64 + mi * 16 + (lane >> 2) + half * 8;
                int bidx = m >> 8, n = m & 255;
                float2 o;
                o.x = R.c[mi][ni][half * 2 + 0] + b0;
                o.y = R.c[mi][ni][half * 2 + 1] + b1;
                *(float2*)(dst + ((size_t)((bidx * kH + h) * kN + n)) * kHD + d) = o;
            }
        }
    }
}

// ---------------------------------------------------------------------------
// Proj GEMM: grid (1024). out[m][j] from g_ao @ proj_w^T + bias.
// ---------------------------------------------------------------------------
__global__ __launch_bounds__(256) void proj_gemm_kernel(
    const float* __restrict__ w, const float* __restrict__ bias,
    float* __restrict__ out)
{
    int m0 = blockIdx.x * 128;

    MmaAcc R;
    mma_gemm_body(g_ao, w, m0, R);

    int lane = threadIdx.x & 31;
    int wid = threadIdx.x >> 5;
    int wm = wid & 1, wn = wid >> 1;

#pragma unroll
    for (int ni = 0; ni < 4; ni++) {
        int col = wn * 32 + ni * 8 + 2 * (lane & 3);
        float b0 = bias[col], b1 = bias[col + 1];
#pragma unroll
        for (int mi = 0; mi < 4; mi++) {
#pragma unroll
            for (int half = 0; half < 2; half++) {
                int m = m0 + wm * 64 + mi * 16 + (lane >> 2) + half * 8;
                float2 o;
                o.x = R.c[mi][ni][half * 2 + 0] + b0;
                o.y = R.c[mi][ni][half * 2 + 1] + b1;
                *(float2*)(out + (size_t)m * kC + col) = o;
            }
        }
    }
}

// ---------------------------------------------------------------------------
// Attention: one block per (b,h). K,V resident in smem. One thread per query
// row. No max-subtraction (scores bounded, exp safe in fp32).
// bias+mask staged per 32-m chunk, transposed (bm[mc][n], pad 257).
// dyn smem = (16384 + 32*257)*4 = 98432 B  -> 2 blocks/SM.
// ---------------------------------------------------------------------------
#define MCHUNK 32
__global__ __launch_bounds__(256) void attn_kernel(const float* __restrict__ mask)
{
    extern __shared__ float sm[];
    float* Ks = sm;                 // 256*32
    float* Vs = sm + 8192;          // 256*32
    float* bm = sm + 16384;         // 32*257

    int t = threadIdx.x;            // query row
    int bh = blockIdx.x;            // b*4 + h
    int b = bh >> 2, h = bh & 3;
    int w = b & (kNW - 1);

    const float* kptr = g_k + (size_t)bh * kN * kHD;
    const float* vptr = g_v + (size_t)bh * kN * kHD;
#pragma unroll
    for (int i = 0; i < 8; i++) {
        int l = t + 256 * i;        // 0..2047 float4s
        ((float4*)Ks)[l] = ((const float4*)kptr)[l];
        ((float4*)Vs)[l] = ((const float4*)vptr)[l];
    }

    const float scale = 0.17677669529663688f;  // 32^-0.5
    float qv[32];
    {
        const float* qptr = g_q + ((size_t)bh * kN + t) * kHD;
#pragma unroll
        for (int i = 0; i < 8; i++) {
            float4 qq = ((const float4*)qptr)[i];
            qv[4 * i + 0] = qq.x * scale; qv[4 * i + 1] = qq.y * scale;
            qv[4 * i + 2] = qq.z * scale; qv[4 * i + 3] = qq.w * scale;
        }
    }

    float o[32];
#pragma unroll
    for (int i = 0; i < 32; i++) o[i] = 0.f;
    float ls = 0.f;

    const float* bias_h = g_bias + (size_t)h * 65536;
    const float* mask_w = mask + (size_t)w * 65536;

    for (int m0 = 0; m0 < kN; m0 += MCHUNK) {
        __syncthreads();
#pragma unroll
        for (int it = 0; it < 8; it++) {
            int l = t + 256 * it;          // 0..2047
            int mc4 = l & 7, r = l >> 3;   // r: 0..255
            float4 bv = *(const float4*)(bias_h + r * 256 + m0 + mc4 * 4);
            float4 mv = *(const float4*)(mask_w + r * 256 + m0 + mc4 * 4);
            bm[(mc4 * 4 + 0) * 257 + r] = bv.x + mv.x;
            bm[(mc4 * 4 + 1) * 257 + r] = bv.y + mv.y;
            bm[(mc4 * 4 + 2) * 257 + r] = bv.z + mv.z;
            bm[(mc4 * 4 + 3) * 257 + r] = bv.w + mv.w;
        }
        __syncthreads();

#pragma unroll 4
        for (int mc = 0; mc < MCHUNK; mc++) {
            int m = m0 + mc;
            const float* krow = Ks + m * 32;
            float s0 = 0.f, s1 = 0.f, s2 = 0.f, s3 = 0.f;
#pragma unroll
            for (int d4 = 0; d4 < 8; d4++) {
                float4 kk = ((const float4*)krow)[d4];
                s0 += qv[d4 * 4 + 0] * kk.x;
                s1 += qv[d4 * 4 + 1] * kk.y;
                s2 += qv[d4 * 4 + 2] * kk.z;
                s3 += qv[d4 * 4 + 3] * kk.w;
            }
            float s = (s0 + s1) + (s2 + s3) + bm[mc * 257 + t];
            float p = __expf(s);
            ls += p;
            const float* vrow = Vs + m * 32;
#pragma unroll
            for (int d4 = 0; d4 < 8; d4++) {
                float4 vv = ((const float4*)vrow)[d4];
                o[d4 * 4 + 0] += p * vv.x;
                o[d4 * 4 + 1] += p * vv.y;
                o[d4 * 4 + 2] += p * vv.z;
                o[d4 * 4 + 3] += p * vv.w;
            }
        }
    }

    float inv = 1.f / ls;
    float* optr = g_ao + ((size_t)b * kN + t) * kC + h * kHD;
#pragma unroll
    for (int i = 0; i < 8; i++) {
        float4 ov;
        ov.x = o[4 * i + 0] * inv; ov.y = o[4 * i + 1] * inv;
        ov.z = o[4 * i + 2] * inv; ov.w = o[4 * i + 3] * inv;
        ((float4*)optr)[i] = ov;
    }
}

// ---------------------------------------------------------------------------
extern "C" void kernel_launch(void* const* d_in, const int* in_sizes, int n_in,
                              void* d_out, int out_size)
{
    const float* x      = (const float*)d_in[0];
    const float* mask   = (const float*)d_in[1];
    const float* qkv_w  = (const float*)d_in[2];
    const float* qkv_b  = (const float*)d_in[3];
    const float* proj_w = (const float*)d_in[4];
    const float* proj_b = (const float*)d_in[5];
    const float* table  = (const float*)d_in[6];
    const int*   ridx   = (const int*)d_in[7];
    float* out = (float*)d_out;

    (void)in_sizes; (void)n_in; (void)out_size;

    cudaFuncSetAttribute((const void*)qkv_gemm_kernel,
                         cudaFuncAttributeMaxDynamicSharedMemorySize, GEMM_SMEM);
    cudaFuncSetAttribute((const void*)proj_gemm_kernel,
                         cudaFuncAttributeMaxDynamicSharedMemorySize, GEMM_SMEM);
    cudaFuncSetAttribute((const void*)attn_kernel,
                         cudaFuncAttributeMaxDynamicSharedMemorySize, 98432);

    bias_gather_kernel<<<256, 256>>>(table, ridx);
    qkv_gemm_kernel<<<dim3(1024, 3), 256, GEMM_SMEM>>>(x, qkv_w, qkv_b);
    attn_kernel<<<2048, 256, 98432>>>(mask);
    proj_gemm_kernel<<<1024, 256, GEMM_SMEM>>>(proj_w, proj_b, out);
}

// round 6
// speedup vs baseline: 3.1413x; 1.7283x over previous
#include <cuda_runtime.h>
#include <math.h>
#include <stdint.h>

// Problem constants
#define kB   512
#define kN   256
#define kC   128
#define kH   4
#define kHD  32
#define kNW  64

// Scratch (device globals: no runtime allocation allowed)
__device__ __align__(16) float g_q[(size_t)kB * kH * kN * kHD];
__device__ __align__(16) float g_k[(size_t)kB * kH * kN * kHD];
__device__ __align__(16) float g_v[(size_t)kB * kH * kN * kHD];
__device__ __align__(16) float g_ao[(size_t)kB * kN * kC];
__device__ __align__(16) float g_bm[(size_t)kNW * kH * kN * kN];   // 64 MB

// ---------------------------------------------------------------------------
// TF32 helpers
// ---------------------------------------------------------------------------
__device__ __forceinline__ uint32_t f2tf32(float f) {
    uint32_t u;
    asm("cvt.rna.tf32.f32 %0, %1;" : "=r"(u) : "f"(f));
    return u;
}

__device__ __forceinline__ void mma_tf32(
    float* c,
    uint32_t a0, uint32_t a1, uint32_t a2, uint32_t a3,
    uint32_t b0, uint32_t b1)
{
    asm volatile(
        "mma.sync.aligned.m16n8k8.row.col.f32.tf32.tf32.f32 "
        "{%0,%1,%2,%3}, {%4,%5,%6,%7}, {%8,%9}, {%0,%1,%2,%3};"
        : "+f"(c[0]), "+f"(c[1]), "+f"(c[2]), "+f"(c[3])
        : "r"(a0), "r"(a1), "r"(a2), "r"(a3), "r"(b0), "r"(b1));
}

// ---------------------------------------------------------------------------
// bm precompute: g_bm[w][h][n][m] = mask[w][n][m] + table[ridx[n][m]][h]
// grid 16384, block 256; one float4 per thread.
// ---------------------------------------------------------------------------
__global__ __launch_bounds__(256) void bm_kernel(
    const float* __restrict__ mask, const float* __restrict__ table,
    const int* __restrict__ ridx)
{
    int F = blockIdx.x * 256 + threadIdx.x;     // 0..4194303
    int wh = F >> 14;                           // 0..255
    int off = (F & 16383) * 4;                  // 0..65532
    int w = wh >> 2, h = wh & 3;
    float4 mv = *(const float4*)(mask + (size_t)w * 65536 + off);
    int4 ri = *(const int4*)(ridx + off);
    float4 o;
    o.x = mv.x + table[ri.x * kH + h];
    o.y = mv.y + table[ri.y * kH + h];
    o.z = mv.z + table[ri.z * kH + h];
    o.w = mv.w + table[ri.w * kH + h];
    *(float4*)(g_bm + (size_t)wh * 65536 + off) = o;
}

// ---------------------------------------------------------------------------
// TF32 MMA GEMM body (unchanged from R5): C[128m x 128n], A @ B^T.
// ---------------------------------------------------------------------------
#define GBK 32
#define GPAD 36

struct MmaAcc { float c[4][4][4]; };   // [mi][ni][frag]

__device__ __forceinline__ void mma_gemm_body(
    const float* __restrict__ A, const float* __restrict__ B,
    int m0, MmaAcc& R)
{
    extern __shared__ uint32_t smem_u[];
    uint32_t (*As)[128][GPAD] = (uint32_t (*)[128][GPAD])smem_u;
    uint32_t (*Bs)[128][GPAD] = (uint32_t (*)[128][GPAD])(smem_u + 2 * 128 * GPAD);

    int tid = threadIdx.x;
    int lane = tid & 31;
    int wid = tid >> 5;
    int wm = wid & 1;
    int wn = wid >> 1;

    int lrow = tid >> 1;
    int lcol = (tid & 1) * 16;

    const float* aptr = A + (size_t)(m0 + lrow) * kC + lcol;
    const float* bptr = B + (size_t)lrow * kC + lcol;

#pragma unroll
    for (int mi = 0; mi < 4; mi++)
#pragma unroll
        for (int ni = 0; ni < 4; ni++)
#pragma unroll
            for (int f = 0; f < 4; f++) R.c[mi][ni][f] = 0.f;

    {
#pragma unroll
        for (int i = 0; i < 4; i++) {
            float4 av = *(const float4*)(aptr + i * 4);
            float4 bv = *(const float4*)(bptr + i * 4);
            As[0][lrow][lcol + i * 4 + 0] = f2tf32(av.x);
            As[0][lrow][lcol + i * 4 + 1] = f2tf32(av.y);
            As[0][lrow][lcol + i * 4 + 2] = f2tf32(av.z);
            As[0][lrow][lcol + i * 4 + 3] = f2tf32(av.w);
            Bs[0][lrow][lcol + i * 4 + 0] = f2tf32(bv.x);
            Bs[0][lrow][lcol + i * 4 + 1] = f2tf32(bv.y);
            Bs[0][lrow][lcol + i * 4 + 2] = f2tf32(bv.z);
            Bs[0][lrow][lcol + i * 4 + 3] = f2tf32(bv.w);
        }
    }
    __syncthreads();

    int qrow = lane >> 2;
    int qk = lane & 3;

#pragma unroll
    for (int kc = 0; kc < 4; kc++) {
        int cur = kc & 1;
        float4 av[4], bv[4];
        if (kc < 3) {
#pragma unroll
            for (int i = 0; i < 4; i++) {
                av[i] = *(const float4*)(aptr + (kc + 1) * GBK + i * 4);
                bv[i] = *(const float4*)(bptr + (kc + 1) * GBK + i * 4);
            }
        }

#pragma unroll
        for (int k8 = 0; k8 < 4; k8++) {
            int kb = k8 * 8 + qk;
            uint32_t af[4][4], bf[4][2];
#pragma unroll
            for (int mi = 0; mi < 4; mi++) {
                int r = wm * 64 + mi * 16 + qrow;
                af[mi][0] = As[cur][r][kb];
                af[mi][1] = As[cur][r + 8][kb];
                af[mi][2] = As[cur][r][kb + 4];
                af[mi][3] = As[cur][r + 8][kb + 4];
            }
#pragma unroll
            for (int ni = 0; ni < 4; ni++) {
                int r = wn * 32 + ni * 8 + qrow;
                bf[ni][0] = Bs[cur][r][kb];
                bf[ni][1] = Bs[cur][r][kb + 4];
            }
#pragma unroll
            for (int mi = 0; mi < 4; mi++)
#pragma unroll
                for (int ni = 0; ni < 4; ni++)
                    mma_tf32(R.c[mi][ni],
                             af[mi][0], af[mi][1], af[mi][2], af[mi][3],
                             bf[ni][0], bf[ni][1]);
        }

        if (kc < 3) {
            int nxt = cur ^ 1;
#pragma unroll
            for (int i = 0; i < 4; i++) {
                As[nxt][lrow][lcol + i * 4 + 0] = f2tf32(av[i].x);
                As[nxt][lrow][lcol + i * 4 + 1] = f2tf32(av[i].y);
                As[nxt][lrow][lcol + i * 4 + 2] = f2tf32(av[i].z);
                As[nxt][lrow][lcol + i * 4 + 3] = f2tf32(av[i].w);
                Bs[nxt][lrow][lcol + i * 4 + 0] = f2tf32(bv[i].x);
                Bs[nxt][lrow][lcol + i * 4 + 1] = f2tf32(bv[i].y);
                Bs[nxt][lrow][lcol + i * 4 + 2] = f2tf32(bv[i].z);
                Bs[nxt][lrow][lcol + i * 4 + 3] = f2tf32(bv[i].w);
            }
            __syncthreads();
        }
    }
}

#define GEMM_SMEM (2 * 128 * GPAD * 2 * 4)   // 73728 B

// ---------------------------------------------------------------------------
// QKV GEMM: grid (1024, 3). Scatter to [b][h][n][d].
// ---------------------------------------------------------------------------
__global__ __launch_bounds__(256) void qkv_gemm_kernel(
    const float* __restrict__ x, const float* __restrict__ w,
    const float* __restrict__ bias)
{
    int m0 = blockIdx.x * 128;
    int part = blockIdx.y;
    int j0 = part * 128;

    MmaAcc R;
    mma_gemm_body(x, w + (size_t)j0 * kC, m0, R);

    int lane = threadIdx.x & 31;
    int wid = threadIdx.x >> 5;
    int wm = wid & 1, wn = wid >> 1;
    int h = wn;
    float* dst = (part == 0) ? g_q : ((part == 1) ? g_k : g_v);

#pragma unroll
    for (int ni = 0; ni < 4; ni++) {
        int col = wn * 32 + ni * 8 + 2 * (lane & 3);
        int d = col & 31;
        float b0 = bias[j0 + col], b1 = bias[j0 + col + 1];
#pragma unroll
        for (int mi = 0; mi < 4; mi++) {
#pragma unroll
            for (int half = 0; half < 2; half++) {
                int m = m0 + wm * 64 + mi * 16 + (lane >> 2) + half * 8;
                int bidx = m >> 8, n = m & 255;
                float2 o;
                o.x = R.c[mi][ni][half * 2 + 0] + b0;
                o.y = R.c[mi][ni][half * 2 + 1] + b1;
                *(float2*)(dst + ((size_t)((bidx * kH + h) * kN + n)) * kHD + d) = o;
            }
        }
    }
}

// ---------------------------------------------------------------------------
// Proj GEMM: grid (1024). out[m][j] from g_ao @ proj_w^T + bias.
// ---------------------------------------------------------------------------
__global__ __launch_bounds__(256) void proj_gemm_kernel(
    const float* __restrict__ w, const float* __restrict__ bias,
    float* __restrict__ out)
{
    int m0 = blockIdx.x * 128;

    MmaAcc R;
    mma_gemm_body(g_ao, w, m0, R);

    int lane = threadIdx.x & 31;
    int wid = threadIdx.x >> 5;
    int wm = wid & 1, wn = wid >> 1;

#pragma unroll
    for (int ni = 0; ni < 4; ni++) {
        int col = wn * 32 + ni * 8 + 2 * (lane & 3);
        float b0 = bias[col], b1 = bias[col + 1];
#pragma unroll
        for (int mi = 0; mi < 4; mi++) {
#pragma unroll
            for (int half = 0; half < 2; half++) {
                int m = m0 + wm * 64 + mi * 16 + (lane >> 2) + half * 8;
                float2 o;
                o.x = R.c[mi][ni][half * 2 + 0] + b0;
                o.y = R.c[mi][ni][half * 2 + 1] + b1;
                *(float2*)(out + (size_t)m * kC + col) = o;
            }
        }
    }
}

// ---------------------------------------------------------------------------
// Tensor-core attention: one block per (b,h), 8 warps x 32 query rows.
// K,V in smem (tf32, stride 36). Q fragments in registers (scale folded).
// Per 32-key chunk: S = Q*K^T via MMA, +bm (gmem), exp, P -> warp-private
// Ps smem (tf32), O += P*V via MMA. No max subtraction (scores bounded).
// smem: Kt 256*36 + Vt 256*36 + Ps 8*32*36 = 27648 words = 110592 B.
// ---------------------------------------------------------------------------
__global__ __launch_bounds__(256) void attn_mma_kernel()
{
    extern __shared__ uint32_t sm_u[];
    uint32_t* Kt = sm_u;                       // [key][36]
    uint32_t* Vt = sm_u + 256 * 36;            // [key][36]

    int tid = threadIdx.x;
    int lane = tid & 31;
    int wid = tid >> 5;
    int grp = lane >> 2;       // 0..7
    int j = lane & 3;          // 0..3
    uint32_t* Ps = sm_u + 2 * 256 * 36 + wid * (32 * 36);

    int bh = blockIdx.x;
    int b = bh >> 2, h = bh & 3;

    // Stage K,V -> smem tf32
    const float* kp = g_k + (size_t)bh * (kN * kHD);
    const float* vp = g_v + (size_t)bh * (kN * kHD);
#pragma unroll
    for (int i = 0; i < 8; i++) {
        int f4 = tid + 256 * i;        // 0..2047
        int key = f4 >> 3, c = f4 & 7;
        float4 kv = ((const float4*)kp)[f4];
        float4 vv = ((const float4*)vp)[f4];
        uint4 kt, vt;
        kt.x = f2tf32(kv.x); kt.y = f2tf32(kv.y);
        kt.z = f2tf32(kv.z); kt.w = f2tf32(kv.w);
        vt.x = f2tf32(vv.x); vt.y = f2tf32(vv.y);
        vt.z = f2tf32(vv.z); vt.w = f2tf32(vv.w);
        *(uint4*)(Kt + key * 36 + c * 4) = kt;
        *(uint4*)(Vt + key * 36 + c * 4) = vt;
    }

    // Q fragments (scale folded in)
    const float scale = 0.17677669529663688f;  // 32^-0.5
    uint32_t qa[2][4][4];
    const float* qbase = g_q + (size_t)bh * (kN * kHD);
#pragma unroll
    for (int mt = 0; mt < 2; mt++)
#pragma unroll
        for (int ks = 0; ks < 4; ks++) {
            const float* qp = qbase + (wid * 32 + mt * 16 + grp) * kHD + ks * 8 + j;
            qa[mt][ks][0] = f2tf32(qp[0] * scale);
            qa[mt][ks][1] = f2tf32(qp[8 * kHD] * scale);
            qa[mt][ks][2] = f2tf32(qp[4] * scale);
            qa[mt][ks][3] = f2tf32(qp[8 * kHD + 4] * scale);
        }
    __syncthreads();

    float oacc[2][4][4];
#pragma unroll
    for (int mt = 0; mt < 2; mt++)
#pragma unroll
        for (int dt = 0; dt < 4; dt++)
#pragma unroll
            for (int f = 0; f < 4; f++) oacc[mt][dt][f] = 0.f;
    float rs[2][2] = {{0.f, 0.f}, {0.f, 0.f}};

    const float* bmp = g_bm + ((size_t)((b & (kNW - 1)) * kH + h)) * 65536;

#pragma unroll 1
    for (int kc = 0; kc < 8; kc++) {
        // S = Q * K_chunk^T
        float sc[2][4][4];
#pragma unroll
        for (int mt = 0; mt < 2; mt++)
#pragma unroll
            for (int nt = 0; nt < 4; nt++)
#pragma unroll
                for (int f = 0; f < 4; f++) sc[mt][nt][f] = 0.f;

#pragma unroll
        for (int nt = 0; nt < 4; nt++)
#pragma unroll
            for (int ks = 0; ks < 4; ks++) {
                int key = kc * 32 + nt * 8 + grp;
                uint32_t b0 = Kt[key * 36 + ks * 8 + j];
                uint32_t b1 = Kt[key * 36 + ks * 8 + j + 4];
                mma_tf32(sc[0][nt], qa[0][ks][0], qa[0][ks][1],
                         qa[0][ks][2], qa[0][ks][3], b0, b1);
                mma_tf32(sc[1][nt], qa[1][ks][0], qa[1][ks][1],
                         qa[1][ks][2], qa[1][ks][3], b0, b1);
            }

        // bm add + exp + store P (tf32) to warp-private Ps
#pragma unroll
        for (int mt = 0; mt < 2; mt++)
#pragma unroll
            for (int nt = 0; nt < 4; nt++) {
                int row = wid * 32 + mt * 16 + grp;
                int col = kc * 32 + nt * 8 + 2 * j;
                float2 bm0 = *(const float2*)(bmp + row * 256 + col);
                float2 bm1 = *(const float2*)(bmp + (row + 8) * 256 + col);
                float p0 = __expf(sc[mt][nt][0] + bm0.x);
                float p1 = __expf(sc[mt][nt][1] + bm0.y);
                float p2 = __expf(sc[mt][nt][2] + bm1.x);
                float p3 = __expf(sc[mt][nt][3] + bm1.y);
                rs[mt][0] += p0 + p1;
                rs[mt][1] += p2 + p3;
                int lr = mt * 16 + grp, lc = nt * 8 + 2 * j;
                Ps[lr * 36 + lc] = f2tf32(p0);
                Ps[lr * 36 + lc + 1] = f2tf32(p1);
                Ps[(lr + 8) * 36 + lc] = f2tf32(p2);
                Ps[(lr + 8) * 36 + lc + 1] = f2tf32(p3);
            }
        __syncwarp();

        // O += P * V_chunk
#pragma unroll
        for (int ks = 0; ks < 4; ks++) {
            uint32_t a0[4], a1[4];
            a0[0] = Ps[grp * 36 + ks * 8 + j];
            a0[1] = Ps[(grp + 8) * 36 + ks * 8 + j];
            a0[2] = Ps[grp * 36 + ks * 8 + j + 4];
            a0[3] = Ps[(grp + 8) * 36 + ks * 8 + j + 4];
            a1[0] = Ps[(grp + 16) * 36 + ks * 8 + j];
            a1[1] = Ps[(grp + 24) * 36 + ks * 8 + j];
            a1[2] = Ps[(grp + 16) * 36 + ks * 8 + j + 4];
            a1[3] = Ps[(grp + 24) * 36 + ks * 8 + j + 4];
#pragma unroll
            for (int dt = 0; dt < 4; dt++) {
                int kb = kc * 32 + ks * 8;
                uint32_t b0 = Vt[(kb + j) * 36 + dt * 8 + grp];
                uint32_t b1 = Vt[(kb + j + 4) * 36 + dt * 8 + grp];
                mma_tf32(oacc[0][dt], a0[0], a0[1], a0[2], a0[3], b0, b1);
                mma_tf32(oacc[1][dt], a1[0], a1[1], a1[2], a1[3], b0, b1);
            }
        }
        __syncwarp();
    }

    // Row-sum reduce across the quad (lanes sharing a row) and normalize
#pragma unroll
    for (int mt = 0; mt < 2; mt++)
#pragma unroll
        for (int hf = 0; hf < 2; hf++) {
            float v = rs[mt][hf];
            v += __shfl_xor_sync(0xFFFFFFFF, v, 1);
            v += __shfl_xor_sync(0xFFFFFFFF, v, 2);
            rs[mt][hf] = 1.f / v;
        }

#pragma unroll
    for (int mt = 0; mt < 2; mt++) {
        int row = wid * 32 + mt * 16 + grp;
#pragma unroll
        for (int dt = 0; dt < 4; dt++) {
            int col = h * 32 + dt * 8 + 2 * j;
            float2 o0, o1;
            o0.x = oacc[mt][dt][0] * rs[mt][0];
            o0.y = oacc[mt][dt][1] * rs[mt][0];
            o1.x = oacc[mt][dt][2] * rs[mt][1];
            o1.y = oacc[mt][dt][3] * rs[mt][1];
            *(float2*)(g_ao + ((size_t)b * 256 + row) * kC + col) = o0;
            *(float2*)(g_ao + ((size_t)b * 256 + row + 8) * kC + col) = o1;
        }
    }
}

#define ATTN_SMEM ((2 * 256 * 36 + 8 * 32 * 36) * 4)   // 110592 B

// ---------------------------------------------------------------------------
extern "C" void kernel_launch(void* const* d_in, const int* in_sizes, int n_in,
                              void* d_out, int out_size)
{
    const float* x      = (const float*)d_in[0];
    const float* mask   = (const float*)d_in[1];
    const float* qkv_w  = (const float*)d_in[2];
    const float* qkv_b  = (const float*)d_in[3];
    const float* proj_w = (const float*)d_in[4];
    const float* proj_b = (const float*)d_in[5];
    const float* table  = (const float*)d_in[6];
    const int*   ridx   = (const int*)d_in[7];
    float* out = (float*)d_out;

    (void)in_sizes; (void)n_in; (void)out_size;

    cudaFuncSetAttribute((const void*)qkv_gemm_kernel,
                         cudaFuncAttributeMaxDynamicSharedMemorySize, GEMM_SMEM);
    cudaFuncSetAttribute((const void*)proj_gemm_kernel,
                         cudaFuncAttributeMaxDynamicSharedMemorySize, GEMM_SMEM);
    cudaFuncSetAttribute((const void*)attn_mma_kernel,
                         cudaFuncAttributeMaxDynamicSharedMemorySize, ATTN_SMEM);

    bm_kernel<<<16384, 256>>>(mask, table, ridx);
    qkv_gemm_kernel<<<dim3(1024, 3), 256, GEMM_SMEM>>>(x, qkv_w, qkv_b);
    attn_mma_kernel<<<2048, 256, ATTN_SMEM>>>();
    proj_gemm_kernel<<<1024, 256, GEMM_SMEM>>>(proj_w, proj_b, out);
}

// round 7
// speedup vs baseline: 3.4367x; 1.0940x over previous
#include <cuda_runtime.h>
#include <math.h>
#include <stdint.h>

// Problem constants
#define kB   512
#define kN   256
#define kC   128
#define kH   4
#define kHD  32
#define kNW  64

// Scratch (device globals: no runtime allocation allowed)
__device__ __align__(16) float g_q[(size_t)kB * kH * kN * kHD];
__device__ __align__(16) float g_k[(size_t)kB * kH * kN * kHD];
__device__ __align__(16) float g_v[(size_t)kB * kH * kN * kHD];
__device__ __align__(16) float g_ao[(size_t)kB * kN * kC];
__device__ __align__(16) float g_bm[(size_t)kNW * kH * kN * kN];   // 64 MB

// ---------------------------------------------------------------------------
// TF32 / ldmatrix helpers
// ---------------------------------------------------------------------------
__device__ __forceinline__ uint32_t f2tf32(float f) {
    uint32_t u;
    asm("cvt.rna.tf32.f32 %0, %1;" : "=r"(u) : "f"(f));
    return u;
}

__device__ __forceinline__ void mma_tf32(
    float* c,
    uint32_t a0, uint32_t a1, uint32_t a2, uint32_t a3,
    uint32_t b0, uint32_t b1)
{
    asm volatile(
        "mma.sync.aligned.m16n8k8.row.col.f32.tf32.tf32.f32 "
        "{%0,%1,%2,%3}, {%4,%5,%6,%7}, {%8,%9}, {%0,%1,%2,%3};"
        : "+f"(c[0]), "+f"(c[1]), "+f"(c[2]), "+f"(c[3])
        : "r"(a0), "r"(a1), "r"(a2), "r"(a3), "r"(b0), "r"(b1));
}

__device__ __forceinline__ uint32_t smem_u32(const void* p) {
    return (uint32_t)__cvta_generic_to_shared(p);
}

__device__ __forceinline__ void ldsm_x4(
    uint32_t& r0, uint32_t& r1, uint32_t& r2, uint32_t& r3, uint32_t a)
{
    asm volatile("ldmatrix.sync.aligned.m8n8.x4.shared.b16 {%0,%1,%2,%3}, [%4];"
        : "=r"(r0), "=r"(r1), "=r"(r2), "=r"(r3) : "r"(a));
}

// ---------------------------------------------------------------------------
// bm precompute: g_bm[w][h][n][m] = mask[w][n][m] + table[ridx[n][m]][h]
// ---------------------------------------------------------------------------
__global__ __launch_bounds__(256) void bm_kernel(
    const float* __restrict__ mask, const float* __restrict__ table,
    const int* __restrict__ ridx)
{
    int F = blockIdx.x * 256 + threadIdx.x;     // 0..4194303
    int wh = F >> 14;                           // 0..255
    int off = (F & 16383) * 4;                  // 0..65532
    int w = wh >> 2, h = wh & 3;
    float4 mv = *(const float4*)(mask + (size_t)w * 65536 + off);
    int4 ri = *(const int4*)(ridx + off);
    float4 o;
    o.x = mv.x + table[ri.x * kH + h];
    o.y = mv.y + table[ri.y * kH + h];
    o.z = mv.z + table[ri.z * kH + h];
    o.w = mv.w + table[ri.w * kH + h];
    *(float4*)(g_bm + (size_t)wh * 65536 + off) = o;
}

// ---------------------------------------------------------------------------
// TF32 MMA GEMM body: C[128m x 128n], A @ B^T, ldmatrix fragment loads.
// smem: As[2][128][36] + Bs[2][128][36] uint32 = 73728 B.
// ---------------------------------------------------------------------------
#define GBK 32
#define GPAD 36

struct MmaAcc { float c[4][4][4]; };   // [mi][ni][frag]

__device__ __forceinline__ void mma_gemm_body(
    const float* __restrict__ A, const float* __restrict__ B,
    int m0, MmaAcc& R)
{
    extern __shared__ uint32_t smem_u[];
    uint32_t (*As)[128][GPAD] = (uint32_t (*)[128][GPAD])smem_u;
    uint32_t (*Bs)[128][GPAD] = (uint32_t (*)[128][GPAD])(smem_u + 2 * 128 * GPAD);

    int tid = threadIdx.x;
    int lane = tid & 31;
    int wid = tid >> 5;
    int wm = wid & 1;
    int wn = wid >> 1;

    int lrow = tid >> 1;
    int lcol = (tid & 1) * 16;

    const float* aptr = A + (size_t)(m0 + lrow) * kC + lcol;
    const float* bptr = B + (size_t)lrow * kC + lcol;

#pragma unroll
    for (int mi = 0; mi < 4; mi++)
#pragma unroll
        for (int ni = 0; ni < 4; ni++)
#pragma unroll
            for (int f = 0; f < 4; f++) R.c[mi][ni][f] = 0.f;

    // ldmatrix lane address components
    int lr8 = lane & 7;
    int g = lane >> 3;          // 0..3
    // A x4 (per mi): row = wm*64 + mi*16 + lr8 + (g&1)*8, col = k8*8 + (g>>1)*4
    uint32_t a_base = smem_u32(&As[0][wm * 64 + lr8 + (g & 1) * 8][(g >> 1) * 4]);
    // B x4 (per ni0): row = wn*32 + (ni0 + (g>>1))*8 + lr8, col = k8*8 + (g&1)*4
    uint32_t b_base = smem_u32(&Bs[0][wn * 32 + (g >> 1) * 8 + lr8][(g & 1) * 4]);

    // stage chunk 0 (vectorized STS.128)
    {
#pragma unroll
        for (int i = 0; i < 4; i++) {
            float4 av = *(const float4*)(aptr + i * 4);
            float4 bv = *(const float4*)(bptr + i * 4);
            uint4 at, bt;
            at.x = f2tf32(av.x); at.y = f2tf32(av.y);
            at.z = f2tf32(av.z); at.w = f2tf32(av.w);
            bt.x = f2tf32(bv.x); bt.y = f2tf32(bv.y);
            bt.z = f2tf32(bv.z); bt.w = f2tf32(bv.w);
            *(uint4*)(&As[0][lrow][lcol + i * 4]) = at;
            *(uint4*)(&Bs[0][lrow][lcol + i * 4]) = bt;
        }
    }
    __syncthreads();

#pragma unroll
    for (int kc = 0; kc < 4; kc++) {
        int cur = kc & 1;
        uint32_t abufo = (uint32_t)(cur * 128 * GPAD * 4);
        float4 av[4], bv[4];
        if (kc < 3) {
#pragma unroll
            for (int i = 0; i < 4; i++) {
                av[i] = *(const float4*)(aptr + (kc + 1) * GBK + i * 4);
                bv[i] = *(const float4*)(bptr + (kc + 1) * GBK + i * 4);
            }
        }

#pragma unroll
        for (int k8 = 0; k8 < 4; k8++) {
            uint32_t colo = abufo + (uint32_t)(k8 * 8 * 4);
            uint32_t af[4][4], bf[4][2];
#pragma unroll
            for (int mi = 0; mi < 4; mi++)
                ldsm_x4(af[mi][0], af[mi][1], af[mi][2], af[mi][3],
                        a_base + colo + (uint32_t)(mi * 16 * GPAD * 4));
#pragma unroll
            for (int ni0 = 0; ni0 < 4; ni0 += 2)
                ldsm_x4(bf[ni0][0], bf[ni0][1], bf[ni0 + 1][0], bf[ni0 + 1][1],
                        b_base + colo + (uint32_t)(ni0 * 8 * GPAD * 4));
#pragma unroll
            for (int mi = 0; mi < 4; mi++)
#pragma unroll
                for (int ni = 0; ni < 4; ni++)
                    mma_tf32(R.c[mi][ni],
                             af[mi][0], af[mi][1], af[mi][2], af[mi][3],
                             bf[ni][0], bf[ni][1]);
        }

        if (kc < 3) {
            int nxt = cur ^ 1;
#pragma unroll
            for (int i = 0; i < 4; i++) {
                uint4 at, bt;
                at.x = f2tf32(av[i].x); at.y = f2tf32(av[i].y);
                at.z = f2tf32(av[i].z); at.w = f2tf32(av[i].w);
                bt.x = f2tf32(bv[i].x); bt.y = f2tf32(bv[i].y);
                bt.z = f2tf32(bv[i].z); bt.w = f2tf32(bv[i].w);
                *(uint4*)(&As[nxt][lrow][lcol + i * 4]) = at;
                *(uint4*)(&Bs[nxt][lrow][lcol + i * 4]) = bt;
            }
            __syncthreads();
        }
    }
}

#define GEMM_SMEM (2 * 128 * GPAD * 2 * 4)   // 73728 B

// ---------------------------------------------------------------------------
// QKV GEMM: grid (1024, 3). Scatter to [b][h][n][d].
// ---------------------------------------------------------------------------
__global__ __launch_bounds__(256) void qkv_gemm_kernel(
    const float* __restrict__ x, const float* __restrict__ w,
    const float* __restrict__ bias)
{
    int m0 = blockIdx.x * 128;
    int part = blockIdx.y;
    int j0 = part * 128;

    MmaAcc R;
    mma_gemm_body(x, w + (size_t)j0 * kC, m0, R);

    int lane = threadIdx.x & 31;
    int wid = threadIdx.x >> 5;
    int wm = wid & 1, wn = wid >> 1;
    int h = wn;
    float* dst = (part == 0) ? g_q : ((part == 1) ? g_k : g_v);

#pragma unroll
    for (int ni = 0; ni < 4; ni++) {
        int col = wn * 32 + ni * 8 + 2 * (lane & 3);
        int d = col & 31;
        float b0 = bias[j0 + col], b1 = bias[j0 + col + 1];
#pragma unroll
        for (int mi = 0; mi < 4; mi++) {
#pragma unroll
            for (int half = 0; half < 2; half++) {
                int m = m0 + wm * 64 + mi * 16 + (lane >> 2) + half * 8;
                int bidx = m >> 8, n = m & 255;
                float2 o;
                o.x = R.c[mi][ni][half * 2 + 0] + b0;
                o.y = R.c[mi][ni][half * 2 + 1] + b1;
                *(float2*)(dst + ((size_t)((bidx * kH + h) * kN + n)) * kHD + d) = o;
            }
        }
    }
}

// ---------------------------------------------------------------------------
// Proj GEMM: grid (1024). out[m][j] from g_ao @ proj_w^T + bias.
// ---------------------------------------------------------------------------
__global__ __launch_bounds__(256) void proj_gemm_kernel(
    const float* __restrict__ w, const float* __restrict__ bias,
    float* __restrict__ out)
{
    int m0 = blockIdx.x * 128;

    MmaAcc R;
    mma_gemm_body(g_ao, w, m0, R);

    int lane = threadIdx.x & 31;
    int wid = threadIdx.x >> 5;
    int wm = wid & 1, wn = wid >> 1;

#pragma unroll
    for (int ni = 0; ni < 4; ni++) {
        int col = wn * 32 + ni * 8 + 2 * (lane & 3);
        float b0 = bias[col], b1 = bias[col + 1];
#pragma unroll
        for (int mi = 0; mi < 4; mi++) {
#pragma unroll
            for (int half = 0; half < 2; half++) {
                int m = m0 + wm * 64 + mi * 16 + (lane >> 2) + half * 8;
                float2 o;
                o.x = R.c[mi][ni][half * 2 + 0] + b0;
                o.y = R.c[mi][ni][half * 2 + 1] + b1;
                *(float2*)(out + (size_t)m * kC + col) = o;
            }
        }
    }
}

// ---------------------------------------------------------------------------
// Tensor-core attention with ldmatrix fragment loads.
// smem: Kt[256][36] (9216 w) + Vt2[32][260] transposed V (8320 w)
//       + Ps[8 warps][32][36] (9216 w) = 26752 words = 107008 B.
// ---------------------------------------------------------------------------
#define VPAD 260
#define ATTN_SMEM ((256 * 36 + 32 * VPAD + 8 * 32 * 36) * 4)

__global__ __launch_bounds__(256) void attn_mma_kernel()
{
    extern __shared__ uint32_t sm_u[];
    uint32_t* Kt = sm_u;                          // [key][36]
    uint32_t* Vt2 = sm_u + 256 * 36;              // [d][260]
    uint32_t* PsAll = sm_u + 256 * 36 + 32 * VPAD;

    int tid = threadIdx.x;
    int lane = tid & 31;
    int wid = tid >> 5;
    int grp = lane >> 2;       // 0..7
    int j = lane & 3;          // 0..3
    uint32_t* Ps = PsAll + wid * (32 * 36);

    int bh = blockIdx.x;
    int b = bh >> 2, h = bh & 3;

    // Stage K -> Kt[key][36] (tf32, STS.128), V -> Vt2[d][260] (transposed)
    const float* kp = g_k + (size_t)bh * (kN * kHD);
    const float* vp = g_v + (size_t)bh * (kN * kHD);
#pragma unroll
    for (int i = 0; i < 8; i++) {
        int f4 = tid + 256 * i;        // 0..2047
        int key = f4 >> 3, c = (f4 & 7) * 4;
        float4 kv = ((const float4*)kp)[f4];
        float4 vv = ((const float4*)vp)[f4];
        uint4 kt;
        kt.x = f2tf32(kv.x); kt.y = f2tf32(kv.y);
        kt.z = f2tf32(kv.z); kt.w = f2tf32(kv.w);
        *(uint4*)(Kt + key * 36 + c) = kt;
        Vt2[(c + 0) * VPAD + key] = f2tf32(vv.x);
        Vt2[(c + 1) * VPAD + key] = f2tf32(vv.y);
        Vt2[(c + 2) * VPAD + key] = f2tf32(vv.z);
        Vt2[(c + 3) * VPAD + key] = f2tf32(vv.w);
    }

    // Q fragments (scale folded in)
    const float scale = 0.17677669529663688f;  // 32^-0.5
    uint32_t qa[2][4][4];
    const float* qbase = g_q + (size_t)bh * (kN * kHD);
#pragma unroll
    for (int mt = 0; mt < 2; mt++)
#pragma unroll
        for (int ks = 0; ks < 4; ks++) {
            const float* qp = qbase + (wid * 32 + mt * 16 + grp) * kHD + ks * 8 + j;
            qa[mt][ks][0] = f2tf32(qp[0] * scale);
            qa[mt][ks][1] = f2tf32(qp[8 * kHD] * scale);
            qa[mt][ks][2] = f2tf32(qp[4] * scale);
            qa[mt][ks][3] = f2tf32(qp[8 * kHD + 4] * scale);
        }
    __syncthreads();

    // ldmatrix lane addresses
    int lr8 = lane & 7;
    int g = lane >> 3;         // 0..3
    // K b-frag x4: rows kc*32+nt*8+lr8, col g*4 (covers ks0, ks0+1)
    uint32_t k_base = smem_u32(Kt + lr8 * 36 + g * 4);
    // Ps a-frag x4: rows mt*16 + lr8 + (g&1)*8, col ks*8 + (g>>1)*4
    uint32_t p_base = smem_u32(Ps + (lr8 + (g & 1) * 8) * 36 + (g >> 1) * 4);
    // V b-frag x4: rows (dt0+(g>>1))*8+lr8, col kb + (g&1)*4
    uint32_t v_base = smem_u32(Vt2 + ((g >> 1) * 8 + lr8) * VPAD + (g & 1) * 4);

    float oacc[2][4][4];
#pragma unroll
    for (int mt = 0; mt < 2; mt++)
#pragma unroll
        for (int dt = 0; dt < 4; dt++)
#pragma unroll
            for (int f = 0; f < 4; f++) oacc[mt][dt][f] = 0.f;
    float rs[2][2] = {{0.f, 0.f}, {0.f, 0.f}};

    const float* bmp = g_bm + ((size_t)((b & (kNW - 1)) * kH + h)) * 65536;

#pragma unroll 1
    for (int kc = 0; kc < 8; kc++) {
        // S = Q * K_chunk^T
        float sc[2][4][4];
#pragma unroll
        for (int mt = 0; mt < 2; mt++)
#pragma unroll
            for (int nt = 0; nt < 4; nt++)
#pragma unroll
                for (int f = 0; f < 4; f++) sc[mt][nt][f] = 0.f;

#pragma unroll
        for (int nt = 0; nt < 4; nt++) {
            uint32_t bf[4][2];
            uint32_t rowo = (uint32_t)((kc * 32 + nt * 8) * 36 * 4);
            ldsm_x4(bf[0][0], bf[0][1], bf[1][0], bf[1][1], k_base + rowo);
            ldsm_x4(bf[2][0], bf[2][1], bf[3][0], bf[3][1], k_base + rowo + 16 * 4);
#pragma unroll
            for (int ks = 0; ks < 4; ks++) {
                mma_tf32(sc[0][nt], qa[0][ks][0], qa[0][ks][1],
                         qa[0][ks][2], qa[0][ks][3], bf[ks][0], bf[ks][1]);
                mma_tf32(sc[1][nt], qa[1][ks][0], qa[1][ks][1],
                         qa[1][ks][2], qa[1][ks][3], bf[ks][0], bf[ks][1]);
            }
        }

        // bm add + exp + store P (tf32) to warp-private Ps
#pragma unroll
        for (int mt = 0; mt < 2; mt++)
#pragma unroll
            for (int nt = 0; nt < 4; nt++) {
                int row = wid * 32 + mt * 16 + grp;
                int col = kc * 32 + nt * 8 + 2 * j;
                float2 bm0 = *(const float2*)(bmp + row * 256 + col);
                float2 bm1 = *(const float2*)(bmp + (row + 8) * 256 + col);
                float p0 = __expf(sc[mt][nt][0] + bm0.x);
                float p1 = __expf(sc[mt][nt][1] + bm0.y);
                float p2 = __expf(sc[mt][nt][2] + bm1.x);
                float p3 = __expf(sc[mt][nt][3] + bm1.y);
                rs[mt][0] += p0 + p1;
                rs[mt][1] += p2 + p3;
                int lr = mt * 16 + grp, lc = nt * 8 + 2 * j;
                Ps[lr * 36 + lc] = f2tf32(p0);
                Ps[lr * 36 + lc + 1] = f2tf32(p1);
                Ps[(lr + 8) * 36 + lc] = f2tf32(p2);
                Ps[(lr + 8) * 36 + lc + 1] = f2tf32(p3);
            }
        __syncwarp();

        // O += P * V_chunk
#pragma unroll
        for (int ks = 0; ks < 4; ks++) {
            int kb = kc * 32 + ks * 8;
            uint32_t a0[4], a1[4];
            uint32_t pcolo = (uint32_t)(ks * 8 * 4);
            ldsm_x4(a0[0], a0[1], a0[2], a0[3], p_base + pcolo);
            ldsm_x4(a1[0], a1[1], a1[2], a1[3], p_base + pcolo + (uint32_t)(16 * 36 * 4));
            uint32_t bf[4][2];
            uint32_t vcolo = (uint32_t)(kb * 4);
            ldsm_x4(bf[0][0], bf[0][1], bf[1][0], bf[1][1], v_base + vcolo);
            ldsm_x4(bf[2][0], bf[2][1], bf[3][0], bf[3][1],
                    v_base + vcolo + (uint32_t)(16 * VPAD * 4));
#pragma unroll
            for (int dt = 0; dt < 4; dt++) {
                mma_tf32(oacc[0][dt], a0[0], a0[1], a0[2], a0[3], bf[dt][0], bf[dt][1]);
                mma_tf32(oacc[1][dt], a1[0], a1[1], a1[2], a1[3], bf[dt][0], bf[dt][1]);
            }
        }
        __syncwarp();
    }

    // Row-sum reduce across the quad and normalize
#pragma unroll
    for (int mt = 0; mt < 2; mt++)
#pragma unroll
        for (int hf = 0; hf < 2; hf++) {
            float v = rs[mt][hf];
            v += __shfl_xor_sync(0xFFFFFFFF, v, 1);
            v += __shfl_xor_sync(0xFFFFFFFF, v, 2);
            rs[mt][hf] = 1.f / v;
        }

#pragma unroll
    for (int mt = 0; mt < 2; mt++) {
        int row = wid * 32 + mt * 16 + grp;
#pragma unroll
        for (int dt = 0; dt < 4; dt++) {
            int col = h * 32 + dt * 8 + 2 * j;
            float2 o0, o1;
            o0.x = oacc[mt][dt][0] * rs[mt][0];
            o0.y = oacc[mt][dt][1] * rs[mt][0];
            o1.x = oacc[mt][dt][2] * rs[mt][1];
            o1.y = oacc[mt][dt][3] * rs[mt][1];
            *(float2*)(g_ao + ((size_t)b * 256 + row) * kC + col) = o0;
            *(float2*)(g_ao + ((size_t)b * 256 + row + 8) * kC + col) = o1;
        }
    }
}

// ---------------------------------------------------------------------------
extern "C" void kernel_launch(void* const* d_in, const int* in_sizes, int n_in,
                              void* d_out, int out_size)
{
    const float* x      = (const float*)d_in[0];
    const float* mask   = (const float*)d_in[1];
    const float* qkv_w  = (const float*)d_in[2];
    const float* qkv_b  = (const float*)d_in[3];
    const float* proj_w = (const float*)d_in[4];
    const float* proj_b = (const float*)d_in[5];
    const float* table  = (const float*)d_in[6];
    const int*   ridx   = (const int*)d_in[7];
    float* out = (float*)d_out;

    (void)in_sizes; (void)n_in; (void)out_size;

    cudaFuncSetAttribute((const void*)qkv_gemm_kernel,
                         cudaFuncAttributeMaxDynamicSharedMemorySize, GEMM_SMEM);
    cudaFuncSetAttribute((const void*)proj_gemm_kernel,
                         cudaFuncAttributeMaxDynamicSharedMemorySize, GEMM_SMEM);
    cudaFuncSetAttribute((const void*)attn_mma_kernel,
                         cudaFuncAttributeMaxDynamicSharedMemorySize, ATTN_SMEM);

    bm_kernel<<<16384, 256>>>(mask, table, ridx);
    qkv_gemm_kernel<<<dim3(1024, 3), 256, GEMM_SMEM>>>(x, qkv_w, qkv_b);
    attn_mma_kernel<<<2048, 256, ATTN_SMEM>>>();
    proj_gemm_kernel<<<1024, 256, GEMM_SMEM>>>(proj_w, proj_b, out);
}

// round 10
// speedup vs baseline: 3.6492x; 1.0618x over previous
#include <cuda_runtime.h>
#include <math.h>
#include <stdint.h>

// Problem constants
#define kB   512
#define kN   256
#define kC   128
#define kH   4
#define kHD  32
#define kNW  64

// Scratch (device globals: no runtime allocation allowed)
__device__ __align__(16) float g_q[(size_t)kB * kH * kN * kHD];
__device__ __align__(16) float g_k[(size_t)kB * kH * kN * kHD];
__device__ __align__(16) float g_v[(size_t)kB * kH * kN * kHD];
__device__ __align__(16) float g_ao[(size_t)kB * kN * kC];      // tf32-rounded by attn
__device__ __align__(16) float g_bm[(size_t)kNW * kH * kN * kN]; // 64 MB, pre-scaled by log2e
__device__ __align__(16) float g_xt[(size_t)kB * kN * kC];      // tf32-rounded x
__device__ __align__(16) float g_wqkv[3 * kC * kC];             // tf32-rounded qkv_w
__device__ __align__(16) float g_wproj[kC * kC];                // tf32-rounded proj_w

#define LOG2E 1.4426950408889634f

// ---------------------------------------------------------------------------
// TF32 / ldmatrix / cp.async helpers
// ---------------------------------------------------------------------------
__device__ __forceinline__ uint32_t f2tf32(float f) {
    uint32_t u;
    asm("cvt.rna.tf32.f32 %0, %1;" : "=r"(u) : "f"(f));
    return u;
}

__device__ __forceinline__ float ex2f(float x) {
    float y;
    asm("ex2.approx.f32 %0, %1;" : "=f"(y) : "f"(x));
    return y;
}

__device__ __forceinline__ void mma_tf32(
    float* c,
    uint32_t a0, uint32_t a1, uint32_t a2, uint32_t a3,
    uint32_t b0, uint32_t b1)
{
    asm volatile(
        "mma.sync.aligned.m16n8k8.row.col.f32.tf32.tf32.f32 "
        "{%0,%1,%2,%3}, {%4,%5,%6,%7}, {%8,%9}, {%0,%1,%2,%3};"
        : "+f"(c[0]), "+f"(c[1]), "+f"(c[2]), "+f"(c[3])
        : "r"(a0), "r"(a1), "r"(a2), "r"(a3), "r"(b0), "r"(b1));
}

__device__ __forceinline__ uint32_t smem_u32(const void* p) {
    return (uint32_t)__cvta_generic_to_shared(p);
}

__device__ __forceinline__ void ldsm_x4(
    uint32_t& r0, uint32_t& r1, uint32_t& r2, uint32_t& r3, uint32_t a)
{
    asm volatile("ldmatrix.sync.aligned.m8n8.x4.shared.b16 {%0,%1,%2,%3}, [%4];"
        : "=r"(r0), "=r"(r1), "=r"(r2), "=r"(r3) : "r"(a));
}

__device__ __forceinline__ void cp16(uint32_t dst, const void* src) {
    asm volatile("cp.async.cg.shared.global [%0], [%1], 16;" :: "r"(dst), "l"(src));
}
#define CP_COMMIT() asm volatile("cp.async.commit_group;")
#define CP_WAIT(N)  asm volatile("cp.async.wait_group %0;" :: "n"(N))

// ---------------------------------------------------------------------------
// cvt: pre-round x, qkv_w, proj_w to tf32 (stored as fp32 bits).
// ---------------------------------------------------------------------------
#define X_F4  4194304
#define QW_F4 12288
#define PW_F4 4096
__global__ __launch_bounds__(256) void cvt_kernel(
    const float* __restrict__ x, const float* __restrict__ qw,
    const float* __restrict__ pw)
{
    int i = blockIdx.x * 256 + threadIdx.x;
    const float4* src;
    float4* dst;
    int off;
    if (i < X_F4) { src = (const float4*)x; dst = (float4*)g_xt; off = i; }
    else if (i < X_F4 + QW_F4) { src = (const float4*)qw; dst = (float4*)g_wqkv; off = i - X_F4; }
    else if (i < X_F4 + QW_F4 + PW_F4) { src = (const float4*)pw; dst = (float4*)g_wproj; off = i - X_F4 - QW_F4; }
    else return;
    float4 v = src[off];
    float4 o;
    o.x = __uint_as_float(f2tf32(v.x));
    o.y = __uint_as_float(f2tf32(v.y));
    o.z = __uint_as_float(f2tf32(v.z));
    o.w = __uint_as_float(f2tf32(v.w));
    dst[off] = o;
}

// ---------------------------------------------------------------------------
// bm precompute: g_bm[w][h][n][m] = (mask[w][n][m] + table[ridx[n][m]][h])*log2e
// ---------------------------------------------------------------------------
__global__ __launch_bounds__(256) void bm_kernel(
    const float* __restrict__ mask, const float* __restrict__ table,
    const int* __restrict__ ridx)
{
    int F = blockIdx.x * 256 + threadIdx.x;     // 0..4194303
    int wh = F >> 14;                           // 0..255
    int off = (F & 16383) * 4;                  // 0..65532
    int w = wh >> 2, h = wh & 3;
    float4 mv = *(const float4*)(mask + (size_t)w * 65536 + off);
    int4 ri = *(const int4*)(ridx + off);
    float4 o;
    o.x = (mv.x + table[ri.x * kH + h]) * LOG2E;
    o.y = (mv.y + table[ri.y * kH + h]) * LOG2E;
    o.z = (mv.z + table[ri.z * kH + h]) * LOG2E;
    o.w = (mv.w + table[ri.w * kH + h]) * LOG2E;
    *(float4*)(g_bm + (size_t)wh * 65536 + off) = o;
}

// ---------------------------------------------------------------------------
// TF32 MMA GEMM body: C[128m x 128n], A @ B^T.
// Inputs are PRE-ROUNDED tf32 values in fp32 bits -> cp.async staging, MMA
// truncation is exact. 3-stage pipeline, K chunks of 32, ldmatrix frags.
// Stage schedule: k0->s0, k1->s1, k2->s2, k3->s0. Final compute uses s0.
// smem: As[3][128][36] + Bs[3][128][36] = 110592 B.
// ---------------------------------------------------------------------------
#define GPAD 36
#define NSTAGE 3
#define STAGE_W (128 * GPAD)
#define GEMM_SMEM (NSTAGE * 2 * STAGE_W * 4)

struct MmaAcc { float c[4][4][4]; };   // [mi][ni][frag]

__device__ __forceinline__ void gemm_load_stage(
    const float* __restrict__ A, const float* __restrict__ B,
    int m0, int kc, int st, int tid, uint32_t sA, uint32_t sB)
{
#pragma unroll
    for (int i = 0; i < 4; i++) {
        int gx = tid + 256 * i;            // 0..1023
        int r = gx >> 3, c4 = (gx & 7) * 4;
        uint32_t so = (uint32_t)((st * STAGE_W + r * GPAD + c4) * 4);
        cp16(sA + so, A + (size_t)(m0 + r) * kC + kc * 32 + c4);
        cp16(sB + so, B + (size_t)r * kC + kc * 32 + c4);
    }
    CP_COMMIT();
}

__device__ __forceinline__ void gemm_compute_stage(
    int st, uint32_t sA, uint32_t sB, uint32_t a_off, uint32_t b_off, MmaAcc& R)
{
    uint32_t base_a = sA + (uint32_t)(st * STAGE_W * 4) + a_off;
    uint32_t base_b = sB + (uint32_t)(st * STAGE_W * 4) + b_off;
#pragma unroll
    for (int k8 = 0; k8 < 4; k8++) {
        uint32_t colo = (uint32_t)(k8 * 8 * 4);
        uint32_t af[4][4], bf[4][2];
#pragma unroll
        for (int mi = 0; mi < 4; mi++)
            ldsm_x4(af[mi][0], af[mi][1], af[mi][2], af[mi][3],
                    base_a + colo + (uint32_t)(mi * 16 * GPAD * 4));
#pragma unroll
        for (int ni0 = 0; ni0 < 4; ni0 += 2)
            ldsm_x4(bf[ni0][0], bf[ni0][1], bf[ni0 + 1][0], bf[ni0 + 1][1],
                    base_b + colo + (uint32_t)(ni0 * 8 * GPAD * 4));
#pragma unroll
        for (int mi = 0; mi < 4; mi++)
#pragma unroll
            for (int ni = 0; ni < 4; ni++)
                mma_tf32(R.c[mi][ni],
                         af[mi][0], af[mi][1], af[mi][2], af[mi][3],
                         bf[ni][0], bf[ni][1]);
    }
}

__device__ __forceinline__ void mma_gemm_body(
    const float* __restrict__ A, const float* __restrict__ B,
    int m0, MmaAcc& R)
{
    extern __shared__ uint32_t smem_u[];
    uint32_t* As = smem_u;
    uint32_t* Bs = smem_u + NSTAGE * STAGE_W;

    int tid = threadIdx.x;
    int lane = tid & 31;
    int wid = tid >> 5;
    int wm = wid & 1;
    int wn = wid >> 1;

#pragma unroll
    for (int mi = 0; mi < 4; mi++)
#pragma unroll
        for (int ni = 0; ni < 4; ni++)
#pragma unroll
            for (int f = 0; f < 4; f++) R.c[mi][ni][f] = 0.f;

    uint32_t sA = smem_u32(As), sB = smem_u32(Bs);

    int lr8 = lane & 7;
    int g = lane >> 3;
    uint32_t a_off = (uint32_t)(((wm * 64 + lr8 + (g & 1) * 8) * GPAD + (g >> 1) * 4) * 4);
    uint32_t b_off = (uint32_t)(((wn * 32 + (g >> 1) * 8 + lr8) * GPAD + (g & 1) * 4) * 4);

    gemm_load_stage(A, B, m0, 0, 0, tid, sA, sB);
    gemm_load_stage(A, B, m0, 1, 1, tid, sA, sB);

    CP_WAIT(1); __syncthreads();
    gemm_load_stage(A, B, m0, 2, 2, tid, sA, sB);
    gemm_compute_stage(0, sA, sB, a_off, b_off, R);

    CP_WAIT(1); __syncthreads();
    gemm_load_stage(A, B, m0, 3, 0, tid, sA, sB);   // k3 -> stage 0
    gemm_compute_stage(1, sA, sB, a_off, b_off, R);

    CP_WAIT(1); __syncthreads();
    gemm_compute_stage(2, sA, sB, a_off, b_off, R);

    CP_WAIT(0); __syncthreads();
    gemm_compute_stage(0, sA, sB, a_off, b_off, R); // k3 lives in stage 0
}

// ---------------------------------------------------------------------------
// QKV GEMM: grid (1024, 3). A = g_xt, B = g_wqkv. Scatter to [b][h][n][d].
// ---------------------------------------------------------------------------
__global__ __launch_bounds__(256) void qkv_gemm_kernel(const float* __restrict__ bias)
{
    int m0 = blockIdx.x * 128;
    int part = blockIdx.y;
    int j0 = part * 128;

    MmaAcc R;
    mma_gemm_body(g_xt, g_wqkv + (size_t)j0 * kC, m0, R);

    int lane = threadIdx.x & 31;
    int wid = threadIdx.x >> 5;
    int wm = wid & 1, wn = wid >> 1;
    int h = wn;
    float* dst = (part == 0) ? g_q : ((part == 1) ? g_k : g_v);

#pragma unroll
    for (int ni = 0; ni < 4; ni++) {
        int col = wn * 32 + ni * 8 + 2 * (lane & 3);
        int d = col & 31;
        float b0 = bias[j0 + col], b1 = bias[j0 + col + 1];
#pragma unroll
        for (int mi = 0; mi < 4; mi++) {
#pragma unroll
            for (int half = 0; half < 2; half++) {
                int m = m0 + wm * 64 + mi * 16 + (lane >> 2) + half * 8;
                int bidx = m >> 8, n = m & 255;
                float2 o;
                o.x = R.c[mi][ni][half * 2 + 0] + b0;
                o.y = R.c[mi][ni][half * 2 + 1] + b1;
                *(float2*)(dst + ((size_t)((bidx * kH + h) * kN + n)) * kHD + d) = o;
            }
        }
    }
}

// ---------------------------------------------------------------------------
// Proj GEMM: grid (1024). A = g_ao (pre-rounded), B = g_wproj.
// ---------------------------------------------------------------------------
__global__ __launch_bounds__(256) void proj_gemm_kernel(
    const float* __restrict__ bias, float* __restrict__ out)
{
    int m0 = blockIdx.x * 128;

    MmaAcc R;
    mma_gemm_body(g_ao, g_wproj, m0, R);

    int lane = threadIdx.x & 31;
    int wid = threadIdx.x >> 5;
    int wm = wid & 1, wn = wid >> 1;

#pragma unroll
    for (int ni = 0; ni < 4; ni++) {
        int col = wn * 32 + ni * 8 + 2 * (lane & 3);
        float b0 = bias[col], b1 = bias[col + 1];
#pragma unroll
        for (int mi = 0; mi < 4; mi++) {
#pragma unroll
            for (int half = 0; half < 2; half++) {
                int m = m0 + wm * 64 + mi * 16 + (lane >> 2) + half * 8;
                float2 o;
                o.x = R.c[mi][ni][half * 2 + 0] + b0;
                o.y = R.c[mi][ni][half * 2 + 1] + b1;
                *(float2*)(out + (size_t)m * kC + col) = o;
            }
        }
    }
}

// ---------------------------------------------------------------------------
// Tensor-core attention with ldmatrix fragment loads.
// exp path uses ex2 (log2e folded into scale and g_bm). Ps stores uint2.
// Output written tf32-rounded (feeds proj's cp.async path).
// smem: Kt[256][36] + Vt2[32][260] + Ps[8][32][36] = 107008 B.
// ---------------------------------------------------------------------------
#define VPAD 260
#define ATTN_SMEM ((256 * 36 + 32 * VPAD + 8 * 32 * 36) * 4)

__global__ __launch_bounds__(256) void attn_mma_kernel()
{
    extern __shared__ uint32_t sm_u[];
    uint32_t* Kt = sm_u;                          // [key][36]
    uint32_t* Vt2 = sm_u + 256 * 36;              // [d][260]
    uint32_t* PsAll = sm_u + 256 * 36 + 32 * VPAD;

    int tid = threadIdx.x;
    int lane = tid & 31;
    int wid = tid >> 5;
    int grp = lane >> 2;       // 0..7
    int j = lane & 3;          // 0..3
    uint32_t* Ps = PsAll + wid * (32 * 36);

    int bh = blockIdx.x;
    int b = bh >> 2, h = bh & 3;

    // Stage K -> Kt[key][36], V -> Vt2[d][260] (transposed), tf32
    const float* kp = g_k + (size_t)bh * (kN * kHD);
    const float* vp = g_v + (size_t)bh * (kN * kHD);
#pragma unroll
    for (int i = 0; i < 8; i++) {
        int f4 = tid + 256 * i;        // 0..2047
        int key = f4 >> 3, c = (f4 & 7) * 4;
        float4 kv = ((const float4*)kp)[f4];
        float4 vv = ((const float4*)vp)[f4];
        uint4 kt;
        kt.x = f2tf32(kv.x); kt.y = f2tf32(kv.y);
        kt.z = f2tf32(kv.z); kt.w = f2tf32(kv.w);
        *(uint4*)(Kt + key * 36 + c) = kt;
        Vt2[(c + 0) * VPAD + key] = f2tf32(vv.x);
        Vt2[(c + 1) * VPAD + key] = f2tf32(vv.y);
        Vt2[(c + 2) * VPAD + key] = f2tf32(vv.z);
        Vt2[(c + 3) * VPAD + key] = f2tf32(vv.w);
    }

    // Q fragments (scale * log2e folded in)
    const float scale = 0.17677669529663688f * LOG2E;
    uint32_t qa[2][4][4];
    const float* qbase = g_q + (size_t)bh * (kN * kHD);
#pragma unroll
    for (int mt = 0; mt < 2; mt++)
#pragma unroll
        for (int ks = 0; ks < 4; ks++) {
            const float* qp = qbase + (wid * 32 + mt * 16 + grp) * kHD + ks * 8 + j;
            qa[mt][ks][0] = f2tf32(qp[0] * scale);
            qa[mt][ks][1] = f2tf32(qp[8 * kHD] * scale);
            qa[mt][ks][2] = f2tf32(qp[4] * scale);
            qa[mt][ks][3] = f2tf32(qp[8 * kHD + 4] * scale);
        }
    __syncthreads();

    // ldmatrix lane addresses
    int lr8 = lane & 7;
    int g = lane >> 3;
    uint32_t k_base = smem_u32(Kt + lr8 * 36 + g * 4);
    uint32_t p_base = smem_u32(Ps + (lr8 + (g & 1) * 8) * 36 + (g >> 1) * 4);
    uint32_t v_base = smem_u32(Vt2 + ((g >> 1) * 8 + lr8) * VPAD + (g & 1) * 4);

    float oacc[2][4][4];
#pragma unroll
    for (int mt = 0; mt < 2; mt++)
#pragma unroll
        for (int dt = 0; dt < 4; dt++)
#pragma unroll
            for (int f = 0; f < 4; f++) oacc[mt][dt][f] = 0.f;
    float rs[2][2] = {{0.f, 0.f}, {0.f, 0.f}};

    const float* bmp = g_bm + ((size_t)((b & (kNW - 1)) * kH + h)) * 65536;

#pragma unroll 1
    for (int kc = 0; kc < 8; kc++) {
        // S = Q * K_chunk^T
        float sc[2][4][4];
#pragma unroll
        for (int mt = 0; mt < 2; mt++)
#pragma unroll
            for (int nt = 0; nt < 4; nt++)
#pragma unroll
                for (int f = 0; f < 4; f++) sc[mt][nt][f] = 0.f;

#pragma unroll
        for (int nt = 0; nt < 4; nt++) {
            uint32_t bf[4][2];
            uint32_t rowo = (uint32_t)((kc * 32 + nt * 8) * 36 * 4);
            ldsm_x4(bf[0][0], bf[0][1], bf[1][0], bf[1][1], k_base + rowo);
            ldsm_x4(bf[2][0], bf[2][1], bf[3][0], bf[3][1], k_base + rowo + 16 * 4);
#pragma unroll
            for (int ks = 0; ks < 4; ks++) {
                mma_tf32(sc[0][nt], qa[0][ks][0], qa[0][ks][1],
                         qa[0][ks][2], qa[0][ks][3], bf[ks][0], bf[ks][1]);
                mma_tf32(sc[1][nt], qa[1][ks][0], qa[1][ks][1],
                         qa[1][ks][2], qa[1][ks][3], bf[ks][0], bf[ks][1]);
            }
        }

        // bm add + ex2 + store P (tf32, packed uint2) to warp-private Ps
#pragma unroll
        for (int mt = 0; mt < 2; mt++)
#pragma unroll
            for (int nt = 0; nt < 4; nt++) {
                int row = wid * 32 + mt * 16 + grp;
                int col = kc * 32 + nt * 8 + 2 * j;
                float2 bm0 = *(const float2*)(bmp + row * 256 + col);
                float2 bm1 = *(const float2*)(bmp + (row + 8) * 256 + col);
                float p0 = ex2f(sc[mt][nt][0] + bm0.x);
                float p1 = ex2f(sc[mt][nt][1] + bm0.y);
                float p2 = ex2f(sc[mt][nt][2] + bm1.x);
                float p3 = ex2f(sc[mt][nt][3] + bm1.y);
                rs[mt][0] += p0 + p1;
                rs[mt][1] += p2 + p3;
                int lr = mt * 16 + grp, lc = nt * 8 + 2 * j;
                uint2 u0, u1;
                u0.x = f2tf32(p0); u0.y = f2tf32(p1);
                u1.x = f2tf32(p2); u1.y = f2tf32(p3);
                *(uint2*)(Ps + lr * 36 + lc) = u0;
                *(uint2*)(Ps + (lr + 8) * 36 + lc) = u1;
            }
        __syncwarp();

        // O += P * V_chunk
#pragma unroll
        for (int ks = 0; ks < 4; ks++) {
            int kb = kc * 32 + ks * 8;
            uint32_t a0[4], a1[4];
            uint32_t pcolo = (uint32_t)(ks * 8 * 4);
            ldsm_x4(a0[0], a0[1], a0[2], a0[3], p_base + pcolo);
            ldsm_x4(a1[0], a1[1], a1[2], a1[3], p_base + pcolo + (uint32_t)(16 * 36 * 4));
            uint32_t bf[4][2];
            uint32_t vcolo = (uint32_t)(kb * 4);
            ldsm_x4(bf[0][0], bf[0][1], bf[1][0], bf[1][1], v_base + vcolo);
            ldsm_x4(bf[2][0], bf[2][1], bf[3][0], bf[3][1],
                    v_base + vcolo + (uint32_t)(16 * VPAD * 4));
#pragma unroll
            for (int dt = 0; dt < 4; dt++) {
                mma_tf32(oacc[0][dt], a0[0], a0[1], a0[2], a0[3], bf[dt][0], bf[dt][1]);
                mma_tf32(oacc[1][dt], a1[0], a1[1], a1[2], a1[3], bf[dt][0], bf[dt][1]);
            }
        }
        __syncwarp();
    }

    // Row-sum reduce across the quad and normalize; write tf32-rounded.
#pragma unroll
    for (int mt = 0; mt < 2; mt++)
#pragma unroll
        for (int hf = 0; hf < 2; hf++) {
            float v = rs[mt][hf];
            v += __shfl_xor_sync(0xFFFFFFFF, v, 1);
            v += __shfl_xor_sync(0xFFFFFFFF, v, 2);
            rs[mt][hf] = 1.f / v;
        }

#pragma unroll
    for (int mt = 0; mt < 2; mt++) {
        int row = wid * 32 + mt * 16 + grp;
#pragma unroll
        for (int dt = 0; dt < 4; dt++) {
            int col = h * 32 + dt * 8 + 2 * j;
            float2 o0, o1;
            o0.x = __uint_as_float(f2tf32(oacc[mt][dt][0] * rs[mt][0]));
            o0.y = __uint_as_float(f2tf32(oacc[mt][dt][1] * rs[mt][0]));
            o1.x = __uint_as_float(f2tf32(oacc[mt][dt][2] * rs[mt][1]));
            o1.y = __uint_as_float(f2tf32(oacc[mt][dt][3] * rs[mt][1]));
            *(float2*)(g_ao + ((size_t)b * 256 + row) * kC + col) = o0;
            *(float2*)(g_ao + ((size_t)b * 256 + row + 8) * kC + col) = o1;
        }
    }
}

// ---------------------------------------------------------------------------
extern "C" void kernel_launch(void* const* d_in, const int* in_sizes, int n_in,
                              void* d_out, int out_size)
{
    const float* x      = (const float*)d_in[0];
    const float* mask   = (const float*)d_in[1];
    const float* qkv_w  = (const float*)d_in[2];
    const float* qkv_b  = (const float*)d_in[3];
    const float* proj_w = (const float*)d_in[4];
    const float* proj_b = (const float*)d_in[5];
    const float* table  = (const float*)d_in[6];
    const int*   ridx   = (const int*)d_in[7];
    float* out = (float*)d_out;

    (void)in_sizes; (void)n_in; (void)out_size;

    cudaFuncSetAttribute((const void*)qkv_gemm_kernel,
                         cudaFuncAttributeMaxDynamicSharedMemorySize, GEMM_SMEM);
    cudaFuncSetAttribute((const void*)proj_gemm_kernel,
                         cudaFuncAttributeMaxDynamicSharedMemorySize, GEMM_SMEM);
    cudaFuncSetAttribute((const void*)attn_mma_kernel,
                         cudaFuncAttributeMaxDynamicSharedMemorySize, ATTN_SMEM);

    cvt_kernel<<<16448, 256>>>(x, qkv_w, proj_w);
    bm_kernel<<<16384, 256>>>(mask, table, ridx);
    qkv_gemm_kernel<<<dim3(1024, 3), 256, GEMM_SMEM>>>(qkv_b);
    attn_mma_kernel<<<2048, 256, ATTN_SMEM>>>();
    proj_gemm_kernel<<<1024, 256, GEMM_SMEM>>>(proj_b, out);
}